// round 11
// baseline (speedup 1.0000x reference)
#include <cuda_runtime.h>
#include <cuda_bf16.h>
#include <cstdint>

#define MROWS  4096   // B*T
#define DMODEL 1024
#define T_SEQ  2048
#define NB     2
#define NH     16
#define DH     64
#define QSCALE 0.1803368801111244f   // 0.125 * log2(e)

// ---------------- scratch (__device__ globals: allocation-free rule) --------
__device__ __nv_bfloat16 g_Qh[MROWS * DMODEL],  g_Ql[MROWS * DMODEL];
__device__ __nv_bfloat16 g_Kh[MROWS * DMODEL],  g_Kl[MROWS * DMODEL];
__device__ __nv_bfloat16 g_Vh[MROWS * DMODEL],  g_Vl[MROWS * DMODEL];
__device__ float         g_Z [MROWS * DMODEL];

__device__ int8_t   g_xq0[MROWS * DMODEL], g_xq1[MROWS * DMODEL];
__device__ int8_t   g_zq0[MROWS * DMODEL], g_zq1[MROWS * DMODEL];
__device__ float    g_xmax[MROWS], g_zmax[MROWS];
__device__ int8_t   g_W0[4][DMODEL * DMODEL], g_W1[4][DMODEL * DMODEL];
__device__ unsigned g_wmax[4 * DMODEL];

// ---------------------------------------------------------------------------
// PTX helpers
// ---------------------------------------------------------------------------
__device__ __forceinline__ uint32_t smem_u32(const void* p) {
    uint32_t a;
    asm("{ .reg .u64 t; cvta.to.shared.u64 t, %1; cvt.u32.u64 %0, t; }"
        : "=r"(a) : "l"(p));
    return a;
}
__device__ __forceinline__ void cp_async16(uint32_t dst, const void* src) {
    asm volatile("cp.async.cg.shared.global [%0], [%1], 16;" :: "r"(dst), "l"(src));
}
#define CP_COMMIT() asm volatile("cp.async.commit_group;" ::: "memory")
#define CP_WAIT(n)  asm volatile("cp.async.wait_group %0;" :: "n"(n) : "memory")
#define SW128(off)  ((off) ^ (((off) >> 3) & 0x70))

__device__ __forceinline__ void ldsm_x4(uint32_t* r, uint32_t addr) {
    asm volatile("ldmatrix.sync.aligned.m8n8.x4.shared.b16 {%0,%1,%2,%3}, [%4];"
                 : "=r"(r[0]), "=r"(r[1]), "=r"(r[2]), "=r"(r[3]) : "r"(addr));
}
__device__ __forceinline__ void ldsm_x4_t(uint32_t* r, uint32_t addr) {
    asm volatile("ldmatrix.sync.aligned.m8n8.x4.trans.shared.b16 {%0,%1,%2,%3}, [%4];"
                 : "=r"(r[0]), "=r"(r[1]), "=r"(r[2]), "=r"(r[3]) : "r"(addr));
}
__device__ __forceinline__ void mma_bf16(float* c, const uint32_t* a,
                                         uint32_t b0, uint32_t b1) {
    asm volatile(
        "mma.sync.aligned.m16n8k16.row.col.f32.bf16.bf16.f32 "
        "{%0,%1,%2,%3}, {%4,%5,%6,%7}, {%8,%9}, {%0,%1,%2,%3};"
        : "+f"(c[0]), "+f"(c[1]), "+f"(c[2]), "+f"(c[3])
        : "r"(a[0]), "r"(a[1]), "r"(a[2]), "r"(a[3]), "r"(b0), "r"(b1));
}
__device__ __forceinline__ void mma_s8(int* c, const uint32_t* a,
                                       uint32_t b0, uint32_t b1) {
    asm volatile(
        "mma.sync.aligned.m16n8k32.row.col.s32.s8.s8.s32 "
        "{%0,%1,%2,%3}, {%4,%5,%6,%7}, {%8,%9}, {%0,%1,%2,%3};"
        : "+r"(c[0]), "+r"(c[1]), "+r"(c[2]), "+r"(c[3])
        : "r"(a[0]), "r"(a[1]), "r"(a[2]), "r"(a[3]), "r"(b0), "r"(b1));
}
__device__ __forceinline__ float ex2(float x) {
    float r; asm("ex2.approx.f32 %0, %1;" : "=f"(r) : "f"(x)); return r;
}
__device__ __forceinline__ uint32_t split2(float v0, float v1, uint32_t& lo) {
    __nv_bfloat16 h0 = __float2bfloat16_rn(v0), h1 = __float2bfloat16_rn(v1);
    float l0 = v0 - __bfloat162float(h0), l1 = v1 - __bfloat162float(h1);
    __nv_bfloat16 L0 = __float2bfloat16_rn(l0), L1 = __float2bfloat16_rn(l1);
    lo = (uint32_t)__bfloat16_as_ushort(L0) | ((uint32_t)__bfloat16_as_ushort(L1) << 16);
    return (uint32_t)__bfloat16_as_ushort(h0) | ((uint32_t)__bfloat16_as_ushort(h1) << 16);
}
// ABI-proof int -> byte (aarch64: plain char is UNSIGNED; never cast float->char)
__device__ __forceinline__ uint32_t byte_of(int v) { return (uint32_t)(uint8_t)(int8_t)v; }

// ---------------------------------------------------------------------------
// Quantization kernels
// ---------------------------------------------------------------------------
__global__ void zero4k(unsigned* p) { p[blockIdx.x * 1024 + threadIdx.x] = 0; }

// per-column |max| of W[K,N] via uint atomicMax (floats >= 0: order-preserving)
__global__ __launch_bounds__(256) void colmax_k(const float* __restrict__ W,
                                                unsigned* __restrict__ cmax)
{
    __shared__ float sm[8][32];
    const int tx = threadIdx.x, ty = threadIdx.y;
    const int n  = blockIdx.x * 32 + tx;
    const int kb = blockIdx.y * 128;
    float m = 0.f;
#pragma unroll
    for (int j = 0; j < 128; j += 8)
        m = fmaxf(m, fabsf(W[(size_t)(kb + ty + j) * DMODEL + n]));
    sm[ty][tx] = m;
    __syncthreads();
    if (ty == 0) {
#pragma unroll
        for (int r = 1; r < 8; r++) m = fmaxf(m, sm[r][tx]);
        atomicMax(&cmax[n], __float_as_uint(m));
    }
}

// W[K,N] fp32 -> transposed 2-level int8 [N,K]
__global__ __launch_bounds__(256) void quant_wt(const float* __restrict__ W,
                                                const unsigned* __restrict__ cmax,
                                                int8_t* __restrict__ Wq0,
                                                int8_t* __restrict__ Wq1)
{
    __shared__ float tile[32][33];
    const int tx = threadIdx.x, ty = threadIdx.y;
    const int bn = blockIdx.x * 32, bk = blockIdx.y * 32;
#pragma unroll
    for (int j = 0; j < 32; j += 8)
        tile[ty + j][tx] = W[(size_t)(bk + ty + j) * DMODEL + bn + tx];
    __syncthreads();
#pragma unroll
    for (int j = 0; j < 32; j += 8) {
        int n = bn + ty + j;
        float inv = 126.f / fmaxf(__uint_as_float(cmax[n]), 1e-30f);
        float ff = tile[tx][ty + j] * inv;
        int   a  = (int)rintf(ff);
        int   b  = (int)fminf(fmaxf(rintf((ff - (float)a) * 256.f), -127.f), 127.f);
        Wq0[(size_t)n * DMODEL + bk + tx] = (int8_t)a;
        Wq1[(size_t)n * DMODEL + bk + tx] = (int8_t)b;
    }
}

// per-row quantize fp32 [M,1024] -> q0,q1 + rmax. One block per row.
__global__ __launch_bounds__(256) void quant_row(const float* __restrict__ src,
                                                 int8_t* __restrict__ q0,
                                                 int8_t* __restrict__ q1,
                                                 float* __restrict__ rmax)
{
    __shared__ float sm[8];
    const int r = blockIdx.x, tid = threadIdx.x;
    float4 v = ((const float4*)src)[r * 256 + tid];
    float f[4] = {v.x, v.y, v.z, v.w};
    float m = fmaxf(fmaxf(fabsf(f[0]), fabsf(f[1])), fmaxf(fabsf(f[2]), fabsf(f[3])));
#pragma unroll
    for (int s = 16; s; s >>= 1) m = fmaxf(m, __shfl_xor_sync(0xffffffff, m, s));
    if ((tid & 31) == 0) sm[tid >> 5] = m;
    __syncthreads();
    float bm = fmaxf(fmaxf(fmaxf(sm[0], sm[1]), fmaxf(sm[2], sm[3])),
                     fmaxf(fmaxf(sm[4], sm[5]), fmaxf(sm[6], sm[7])));
    bm = fmaxf(bm, 1e-30f);
    if (tid == 0) rmax[r] = bm;
    float inv = 126.f / bm;
    uint32_t p0 = 0, p1 = 0;
#pragma unroll
    for (int k = 0; k < 4; k++) {
        float ff = f[k] * inv;
        int   a  = (int)rintf(ff);
        int   b  = (int)fminf(fmaxf(rintf((ff - (float)a) * 256.f), -127.f), 127.f);
        p0 |= byte_of(a) << (8 * k);
        p1 |= byte_of(b) << (8 * k);
    }
    ((uint32_t*)q0)[r * 256 + tid] = p0;
    ((uint32_t*)q1)[r * 256 + tid] = p1;
}

// ---------------------------------------------------------------------------
// int8 IMMA GEMM, 2-level fixed point: C = A[M,K] * B[N,K]^T * scales.
// CTA 128x64, BK=64, 8 warps (4m x 2n -> warp m32n32), 2-stage cp.async.
// acc0 = q0*p0 ; acc1 = q0*p1 + q1*p0 ; C = sr*sc*(acc0 + acc1/256).
// ---------------------------------------------------------------------------
#define S8_STAGE 30720u        // A0,A1: 128*80 each; B0,B1: 64*80 each
#define S8_NST   (DMODEL / 64) // 16

extern __shared__ char dyn_smem[];

__global__ __launch_bounds__(256, 2) void gemm_s8(
    const int8_t* __restrict__ A0, const int8_t* __restrict__ A1,
    const float* __restrict__ amax,
    const int8_t* __restrict__ B0, const int8_t* __restrict__ B1,
    const unsigned* __restrict__ bmax,
    float* __restrict__ Cf, __nv_bfloat16* __restrict__ Ch,
    __nv_bfloat16* __restrict__ Cl, float scale)
{
    const uint32_t sb = smem_u32(dyn_smem);
    const int tid  = threadIdx.x;
    const int lane = tid & 31;
    const int wid  = tid >> 5;
    const int m0w  = (wid & 3) * 32;
    const int n0w  = (wid >> 2) * 32;
    const int row0 = blockIdx.y * 128;
    const int col0 = blockIdx.x * 64;

    int acc0[2][4][4], acc1[2][4][4];
#pragma unroll
    for (int a = 0; a < 2; a++)
#pragma unroll
        for (int b = 0; b < 4; b++)
#pragma unroll
            for (int d = 0; d < 4; d++) { acc0[a][b][d] = 0; acc1[a][b][d] = 0; }

    const int a_row = lane & 15;
    const int b_row = (lane & 7) + 8 * (lane >> 4);

    auto load_stage = [&](int s) {
        const uint32_t base = sb + (uint32_t)(s & 1) * S8_STAGE;
        const int k0 = s * 64;
#pragma unroll
        for (int i = 0; i < 2; i++) {
            int f = tid + i * 256, r = f >> 2, ch = f & 3;
            uint32_t d = base + (uint32_t)(r * 80 + ch * 16);
            size_t g = (size_t)(row0 + r) * DMODEL + k0 + ch * 16;
            cp_async16(d,          A0 + g);
            cp_async16(d + 10240u, A1 + g);
        }
        {
            int r = tid >> 2, ch = tid & 3;
            uint32_t d = base + 20480u + (uint32_t)(r * 80 + ch * 16);
            size_t g = (size_t)(col0 + r) * DMODEL + k0 + ch * 16;
            cp_async16(d,         B0 + g);
            cp_async16(d + 5120u, B1 + g);
        }
        CP_COMMIT();
    };

    load_stage(0);

    for (int s = 0; s < S8_NST; s++) {
        if (s + 1 < S8_NST) { load_stage(s + 1); CP_WAIT(1); }
        else                 { CP_WAIT(0); }
        __syncthreads();

        const uint32_t base = sb + (uint32_t)(s & 1) * S8_STAGE;
        const uint32_t A0b = base, A1b = base + 10240u;
        const uint32_t B0b = base + 20480u, B1b = base + 25600u;

#pragma unroll
        for (int kk = 0; kk < 64; kk += 32) {
            uint32_t a0f[2][4], a1f[2][4];
#pragma unroll
            for (int mi = 0; mi < 2; mi++) {
                uint32_t off = (uint32_t)((m0w + mi * 16 + a_row) * 80 +
                                          kk + (lane >> 4) * 16);
                ldsm_x4(a0f[mi], A0b + off);
                ldsm_x4(a1f[mi], A1b + off);
            }
#pragma unroll
            for (int ng = 0; ng < 2; ng++) {
                uint32_t boff = (uint32_t)((n0w + ng * 16 + b_row) * 80 +
                                           kk + ((lane >> 3) & 1) * 16);
                uint32_t b0f[4], b1f[4];
                ldsm_x4(b0f, B0b + boff);
                ldsm_x4(b1f, B1b + boff);
#pragma unroll
                for (int mi = 0; mi < 2; mi++) {
                    mma_s8(acc0[mi][2 * ng],     a0f[mi], b0f[0], b0f[1]);
                    mma_s8(acc0[mi][2 * ng + 1], a0f[mi], b0f[2], b0f[3]);
                    mma_s8(acc1[mi][2 * ng],     a0f[mi], b1f[0], b1f[1]);
                    mma_s8(acc1[mi][2 * ng + 1], a0f[mi], b1f[2], b1f[3]);
                    mma_s8(acc1[mi][2 * ng],     a1f[mi], b0f[0], b0f[1]);
                    mma_s8(acc1[mi][2 * ng + 1], a1f[mi], b0f[2], b0f[3]);
                }
            }
        }
        __syncthreads();
    }

    // epilogue: C = sr*sc*(acc0 + acc1/256); scale folded into sr
    const float i126 = 1.f / 126.f, i256 = 1.f / 256.f;
#pragma unroll
    for (int mi = 0; mi < 2; mi++) {
        int r = row0 + m0w + mi * 16 + (lane >> 2);
        float sr0 = amax[r]     * i126 * scale;
        float sr1 = amax[r + 8] * i126 * scale;
#pragma unroll
        for (int nj = 0; nj < 4; nj++) {
            int c = col0 + n0w + nj * 8 + (lane & 3) * 2;
            float sc0 = __uint_as_float(bmax[c])     * i126;
            float sc1 = __uint_as_float(bmax[c + 1]) * i126;
            float v0 = ((float)acc0[mi][nj][0] + (float)acc1[mi][nj][0] * i256) * sr0 * sc0;
            float v1 = ((float)acc0[mi][nj][1] + (float)acc1[mi][nj][1] * i256) * sr0 * sc1;
            float v2 = ((float)acc0[mi][nj][2] + (float)acc1[mi][nj][2] * i256) * sr1 * sc0;
            float v3 = ((float)acc0[mi][nj][3] + (float)acc1[mi][nj][3] * i256) * sr1 * sc1;
            if (Ch) {
                uint32_t lo0, lo1;
                uint32_t hi0 = split2(v0, v1, lo0);
                uint32_t hi1 = split2(v2, v3, lo1);
                *(uint32_t*)&Ch[(size_t)r * DMODEL + c]       = hi0;
                *(uint32_t*)&Cl[(size_t)r * DMODEL + c]       = lo0;
                *(uint32_t*)&Ch[(size_t)(r + 8) * DMODEL + c] = hi1;
                *(uint32_t*)&Cl[(size_t)(r + 8) * DMODEL + c] = lo1;
            } else {
                *(float2*)&Cf[(size_t)r * DMODEL + c]       = make_float2(v0, v1);
                *(float2*)&Cf[(size_t)(r + 8) * DMODEL + c] = make_float2(v2, v3);
            }
        }
    }
}

// ---------------------------------------------------------------------------
// FlashAttention-2 on mma.sync (unchanged core from R8 WIN; epilogue -> fp32 Z)
// ---------------------------------------------------------------------------
#define ATT_QH   0u
#define ATT_QL   16384u
#define ATT_BUF  32768u
#define ATT_SMEM 98304u

__global__ __launch_bounds__(256, 2) void attn_tc()
{
    const uint32_t sb = smem_u32(dyn_smem);
    const int tid  = threadIdx.x;
    const int lane = tid & 31;
    const int wid  = tid >> 5;
    const int m0   = wid * 16;
    const int bh   = blockIdx.y;
    const int base = (bh >> 4) * T_SEQ;
    const int h64  = (bh & 15) * DH;
    const int qb   = ((int)gridDim.x - 1 - (int)blockIdx.x) * 128;
    const int ntiles = qb / 64 + 2;

#pragma unroll
    for (int i = 0; i < 4; i++) {
        int f = tid + 256 * i;
        int r = f >> 3, ch = f & 7;
        uint32_t off = SW128((uint32_t)(r * 128 + ch * 16));
        size_t g = (size_t)(base + qb + r) * DMODEL + h64 + ch * 8;
        cp_async16(sb + ATT_QH + off, &g_Qh[g]);
        cp_async16(sb + ATT_QL + off, &g_Ql[g]);
    }
    CP_COMMIT();

    auto load_kv = [&](int t) {
        const uint32_t bufb = sb + ATT_BUF + (uint32_t)(t & 1) * 32768u;
        const int kt = t * 64;
#pragma unroll
        for (int i = 0; i < 2; i++) {
            int f = tid + 256 * i;
            int r = f >> 3, ch = f & 7;
            uint32_t off = SW128((uint32_t)(r * 128 + ch * 16));
            size_t g = (size_t)(base + kt + r) * DMODEL + h64 + ch * 8;
            cp_async16(bufb + off,         &g_Kh[g]);
            cp_async16(bufb + 8192 + off,  &g_Kl[g]);
            cp_async16(bufb + 16384 + off, &g_Vh[g]);
            cp_async16(bufb + 24576 + off, &g_Vl[g]);
        }
        CP_COMMIT();
    };

    load_kv(0);

    const int a_row = lane & 15;
    const int a_col = 8 * (lane >> 4);
    const int b_row = (lane & 7) + 8 * (lane >> 4);
    const int b_col = 8 * ((lane >> 3) & 1);

    CP_WAIT(1);
    __syncthreads();
    uint32_t qh[4][4], ql[4][4];
#pragma unroll
    for (int ks = 0; ks < 4; ks++) {
        uint32_t off = SW128((uint32_t)((m0 + a_row) * 128 + (ks * 16 + a_col) * 2));
        ldsm_x4(qh[ks], sb + ATT_QH + off);
        ldsm_x4(ql[ks], sb + ATT_QL + off);
    }

    float o[8][4];
#pragma unroll
    for (int b = 0; b < 8; b++)
#pragma unroll
        for (int d = 0; d < 4; d++) o[b][d] = 0.f;
    float mrow[2] = {-1e30f, -1e30f};
    float lrow[2] = {0.f, 0.f};

    for (int t = 0; t < ntiles; t++) {
        if (t + 1 < ntiles) { load_kv(t + 1); CP_WAIT(1); }
        else                 { CP_WAIT(0); }
        __syncthreads();

        const uint32_t bufb = sb + ATT_BUF + (uint32_t)(t & 1) * 32768u;
        const uint32_t KHb = bufb, KLb = bufb + 8192;
        const uint32_t VHb = bufb + 16384, VLb = bufb + 24576;
        const int kt = t * 64;

        float s[8][4];
#pragma unroll
        for (int b = 0; b < 8; b++)
#pragma unroll
            for (int d = 0; d < 4; d++) s[b][d] = 0.f;

#pragma unroll
        for (int ks = 0; ks < 4; ks++) {
#pragma unroll
            for (int jp = 0; jp < 4; jp++) {
                uint32_t boff = SW128((uint32_t)((jp * 16 + b_row) * 128 +
                                                 (ks * 16 + b_col) * 2));
                uint32_t kh[4], kl[4];
                ldsm_x4(kh, KHb + boff);
                ldsm_x4(kl, KLb + boff);
                mma_bf16(s[2 * jp],     qh[ks], kh[0], kh[1]);
                mma_bf16(s[2 * jp + 1], qh[ks], kh[2], kh[3]);
                mma_bf16(s[2 * jp],     qh[ks], kl[0], kl[1]);
                mma_bf16(s[2 * jp + 1], qh[ks], kl[2], kl[3]);
                mma_bf16(s[2 * jp],     ql[ks], kh[0], kh[1]);
                mma_bf16(s[2 * jp + 1], ql[ks], kh[2], kh[3]);
            }
        }

        if (t >= ntiles - 2) {
            int rlo = qb + m0 + (lane >> 2);
#pragma unroll
            for (int j = 0; j < 8; j++) {
                int c0 = kt + j * 8 + (lane & 3) * 2;
                if (c0 > rlo)         s[j][0] = -1e30f;
                if (c0 + 1 > rlo)     s[j][1] = -1e30f;
                if (c0 > rlo + 8)     s[j][2] = -1e30f;
                if (c0 + 1 > rlo + 8) s[j][3] = -1e30f;
            }
        }

        {
            float mx0 = -1e30f, mx1 = -1e30f;
#pragma unroll
            for (int j = 0; j < 8; j++) {
                mx0 = fmaxf(mx0, fmaxf(s[j][0], s[j][1]));
                mx1 = fmaxf(mx1, fmaxf(s[j][2], s[j][3]));
            }
            mx0 = fmaxf(mx0, __shfl_xor_sync(0xffffffff, mx0, 1));
            mx0 = fmaxf(mx0, __shfl_xor_sync(0xffffffff, mx0, 2));
            mx1 = fmaxf(mx1, __shfl_xor_sync(0xffffffff, mx1, 1));
            mx1 = fmaxf(mx1, __shfl_xor_sync(0xffffffff, mx1, 2));
            float mn0 = fmaxf(mrow[0], mx0), mn1 = fmaxf(mrow[1], mx1);
            float c0 = ex2(mrow[0] - mn0),   c1 = ex2(mrow[1] - mn1);
            mrow[0] = mn0; mrow[1] = mn1;
            lrow[0] *= c0; lrow[1] *= c1;
#pragma unroll
            for (int j = 0; j < 8; j++) {
                o[j][0] *= c0; o[j][1] *= c0;
                o[j][2] *= c1; o[j][3] *= c1;
            }
            float sum0 = 0.f, sum1 = 0.f;
#pragma unroll
            for (int j = 0; j < 8; j++) {
                float p0 = ex2(s[j][0] - mn0);
                float p1 = ex2(s[j][1] - mn0);
                float p2 = ex2(s[j][2] - mn1);
                float p3 = ex2(s[j][3] - mn1);
                s[j][0] = p0; s[j][1] = p1;
                s[j][2] = p2; s[j][3] = p3;
                sum0 += p0 + p1; sum1 += p2 + p3;
            }
            lrow[0] += sum0; lrow[1] += sum1;
        }

#pragma unroll
        for (int ks = 0; ks < 4; ks++) {
            uint32_t ph[4], pl[4];
            ph[0] = split2(s[2 * ks][0],     s[2 * ks][1],     pl[0]);
            ph[1] = split2(s[2 * ks][2],     s[2 * ks][3],     pl[1]);
            ph[2] = split2(s[2 * ks + 1][0], s[2 * ks + 1][1], pl[2]);
            ph[3] = split2(s[2 * ks + 1][2], s[2 * ks + 1][3], pl[3]);
#pragma unroll
            for (int jp = 0; jp < 4; jp++) {
                uint32_t voff = SW128((uint32_t)((ks * 16 + a_row) * 128 +
                                                 (jp * 16 + a_col) * 2));
                uint32_t vh[4], vl[4];
                ldsm_x4_t(vh, VHb + voff);
                ldsm_x4_t(vl, VLb + voff);
                mma_bf16(o[2 * jp],     ph, vh[0], vh[1]);
                mma_bf16(o[2 * jp + 1], ph, vh[2], vh[3]);
                mma_bf16(o[2 * jp],     ph, vl[0], vl[1]);
                mma_bf16(o[2 * jp + 1], ph, vl[2], vl[3]);
                mma_bf16(o[2 * jp],     pl, vh[0], vh[1]);
                mma_bf16(o[2 * jp + 1], pl, vh[2], vh[3]);
            }
        }
        __syncthreads();
    }

    {
        float l0 = lrow[0], l1 = lrow[1];
        l0 += __shfl_xor_sync(0xffffffff, l0, 1);
        l0 += __shfl_xor_sync(0xffffffff, l0, 2);
        l1 += __shfl_xor_sync(0xffffffff, l1, 1);
        l1 += __shfl_xor_sync(0xffffffff, l1, 2);
        float inv0 = 1.f / l0, inv1 = 1.f / l1;
        size_t rlo = (size_t)(base + qb + m0 + (lane >> 2)) * DMODEL;
        size_t rhi = rlo + 8 * DMODEL;
#pragma unroll
        for (int j = 0; j < 8; j++) {
            int c = h64 + j * 8 + (lane & 3) * 2;
            *(float2*)&g_Z[rlo + c] = make_float2(o[j][0] * inv0, o[j][1] * inv0);
            *(float2*)&g_Z[rhi + c] = make_float2(o[j][2] * inv1, o[j][3] * inv1);
        }
    }
}

// ---------------------------------------------------------------------------
extern "C" void kernel_launch(void* const* d_in, const int* in_sizes, int n_in,
                              void* d_out, int out_size)
{
    const float* x = (const float*)d_in[0];
    const float* W[4] = {(const float*)d_in[1], (const float*)d_in[2],
                         (const float*)d_in[3], (const float*)d_in[4]};
    float* out = (float*)d_out;

    __nv_bfloat16 *Qh, *Ql, *Kh, *Kl, *Vh, *Vl;
    float *Z, *xmax, *zmax;
    int8_t *xq0, *xq1, *zq0, *zq1, *W0, *W1;
    unsigned* wmax;
    cudaGetSymbolAddress((void**)&Qh, g_Qh);   cudaGetSymbolAddress((void**)&Ql, g_Ql);
    cudaGetSymbolAddress((void**)&Kh, g_Kh);   cudaGetSymbolAddress((void**)&Kl, g_Kl);
    cudaGetSymbolAddress((void**)&Vh, g_Vh);   cudaGetSymbolAddress((void**)&Vl, g_Vl);
    cudaGetSymbolAddress((void**)&Z, g_Z);
    cudaGetSymbolAddress((void**)&xq0, g_xq0); cudaGetSymbolAddress((void**)&xq1, g_xq1);
    cudaGetSymbolAddress((void**)&zq0, g_zq0); cudaGetSymbolAddress((void**)&zq1, g_zq1);
    cudaGetSymbolAddress((void**)&xmax, g_xmax);
    cudaGetSymbolAddress((void**)&zmax, g_zmax);
    cudaGetSymbolAddress((void**)&W0, g_W0);
    cudaGetSymbolAddress((void**)&W1, g_W1);
    cudaGetSymbolAddress((void**)&wmax, g_wmax);

    cudaFuncSetAttribute(gemm_s8, cudaFuncAttributeMaxDynamicSharedMemorySize,
                         2 * S8_STAGE);
    cudaFuncSetAttribute(attn_tc, cudaFuncAttributeMaxDynamicSharedMemorySize,
                         ATT_SMEM);

    const size_t WSZ = (size_t)DMODEL * DMODEL;

    // quantize weights (per-column scales) and x (per-row scales)
    zero4k<<<4, 1024>>>(wmax);
    for (int w = 0; w < 4; w++)
        colmax_k<<<dim3(32, 8), dim3(32, 8)>>>(W[w], wmax + w * DMODEL);
    for (int w = 0; w < 4; w++)
        quant_wt<<<dim3(32, 32), dim3(32, 8)>>>(W[w], wmax + w * DMODEL,
                                                W0 + w * WSZ, W1 + w * WSZ);
    quant_row<<<MROWS, 256>>>(x, xq0, xq1, xmax);

    dim3 ggrid(DMODEL / 64, MROWS / 128);   // (16, 32)
    gemm_s8<<<ggrid, 256, 2 * S8_STAGE>>>(xq0, xq1, xmax, W0 + 0 * WSZ, W1 + 0 * WSZ,
                                          wmax + 0 * DMODEL, nullptr, Qh, Ql, QSCALE);
    gemm_s8<<<ggrid, 256, 2 * S8_STAGE>>>(xq0, xq1, xmax, W0 + 1 * WSZ, W1 + 1 * WSZ,
                                          wmax + 1 * DMODEL, nullptr, Kh, Kl, 1.0f);
    gemm_s8<<<ggrid, 256, 2 * S8_STAGE>>>(xq0, xq1, xmax, W0 + 2 * WSZ, W1 + 2 * WSZ,
                                          wmax + 2 * DMODEL, nullptr, Vh, Vl, 1.0f);

    attn_tc<<<dim3(T_SEQ / 128, NB * NH), 256, ATT_SMEM>>>();

    quant_row<<<MROWS, 256>>>(Z, zq0, zq1, zmax);
    gemm_s8<<<ggrid, 256, 2 * S8_STAGE>>>(zq0, zq1, zmax, W0 + 3 * WSZ, W1 + 3 * WSZ,
                                          wmax + 3 * DMODEL, out, nullptr, nullptr, 1.0f);
}

// round 12
// speedup vs baseline: 2.2711x; 2.2711x over previous
#include <cuda_runtime.h>
#include <cuda_bf16.h>
#include <cuda_fp16.h>
#include <cstdint>

#define MROWS  4096   // B*T
#define DMODEL 1024
#define T_SEQ  2048
#define NB     2
#define NH     16
#define DH     64
#define QSCALE 0.1803368801111244f   // 0.125 * log2(e)

// ---------------- scratch (__device__ globals: allocation-free rule) --------
// attention operands stay bf16 hi/lo (validated path)
__device__ __nv_bfloat16 g_Qh[MROWS * DMODEL],  g_Ql[MROWS * DMODEL];
__device__ __nv_bfloat16 g_Kh[MROWS * DMODEL],  g_Kl[MROWS * DMODEL];
__device__ __nv_bfloat16 g_Vh[MROWS * DMODEL],  g_Vl[MROWS * DMODEL];
// GEMM operands fp16: activations split hi/lo (exact), weights single-rounded
__device__ __half g_xh[MROWS * DMODEL], g_xl[MROWS * DMODEL];
__device__ __half g_Zh[MROWS * DMODEL], g_Zl[MROWS * DMODEL];
__device__ __half g_W[4][DMODEL * DMODEL];        // transposed [N,K], fp16

// ---------------------------------------------------------------------------
// PTX helpers (plain sm_103: cp.async, ldmatrix, mma.sync, ex2.approx)
// ---------------------------------------------------------------------------
__device__ __forceinline__ uint32_t smem_u32(const void* p) {
    uint32_t a;
    asm("{ .reg .u64 t; cvta.to.shared.u64 t, %1; cvt.u32.u64 %0, t; }"
        : "=r"(a) : "l"(p));
    return a;
}
__device__ __forceinline__ void cp_async16(uint32_t dst, const void* src) {
    asm volatile("cp.async.cg.shared.global [%0], [%1], 16;" :: "r"(dst), "l"(src));
}
#define CP_COMMIT() asm volatile("cp.async.commit_group;" ::: "memory")
#define CP_WAIT(n)  asm volatile("cp.async.wait_group %0;" :: "n"(n) : "memory")
#define SW128(off)  ((off) ^ (((off) >> 3) & 0x70))

__device__ __forceinline__ void ldsm_x4(uint32_t* r, uint32_t addr) {
    asm volatile("ldmatrix.sync.aligned.m8n8.x4.shared.b16 {%0,%1,%2,%3}, [%4];"
                 : "=r"(r[0]), "=r"(r[1]), "=r"(r[2]), "=r"(r[3]) : "r"(addr));
}
__device__ __forceinline__ void ldsm_x4_t(uint32_t* r, uint32_t addr) {
    asm volatile("ldmatrix.sync.aligned.m8n8.x4.trans.shared.b16 {%0,%1,%2,%3}, [%4];"
                 : "=r"(r[0]), "=r"(r[1]), "=r"(r[2]), "=r"(r[3]) : "r"(addr));
}
__device__ __forceinline__ void mma_bf16(float* c, const uint32_t* a,
                                         uint32_t b0, uint32_t b1) {
    asm volatile(
        "mma.sync.aligned.m16n8k16.row.col.f32.bf16.bf16.f32 "
        "{%0,%1,%2,%3}, {%4,%5,%6,%7}, {%8,%9}, {%0,%1,%2,%3};"
        : "+f"(c[0]), "+f"(c[1]), "+f"(c[2]), "+f"(c[3])
        : "r"(a[0]), "r"(a[1]), "r"(a[2]), "r"(a[3]), "r"(b0), "r"(b1));
}
__device__ __forceinline__ void mma_f16(float* c, const uint32_t* a,
                                        uint32_t b0, uint32_t b1) {
    asm volatile(
        "mma.sync.aligned.m16n8k16.row.col.f32.f16.f16.f32 "
        "{%0,%1,%2,%3}, {%4,%5,%6,%7}, {%8,%9}, {%0,%1,%2,%3};"
        : "+f"(c[0]), "+f"(c[1]), "+f"(c[2]), "+f"(c[3])
        : "r"(a[0]), "r"(a[1]), "r"(a[2]), "r"(a[3]), "r"(b0), "r"(b1));
}
__device__ __forceinline__ float ex2(float x) {
    float r; asm("ex2.approx.f32 %0, %1;" : "=f"(r) : "f"(x)); return r;
}
// bf16 hi/lo pair pack (attention path)
__device__ __forceinline__ uint32_t split2(float v0, float v1, uint32_t& lo) {
    __nv_bfloat16 h0 = __float2bfloat16_rn(v0), h1 = __float2bfloat16_rn(v1);
    float l0 = v0 - __bfloat162float(h0), l1 = v1 - __bfloat162float(h1);
    __nv_bfloat16 L0 = __float2bfloat16_rn(l0), L1 = __float2bfloat16_rn(l1);
    lo = (uint32_t)__bfloat16_as_ushort(L0) | ((uint32_t)__bfloat16_as_ushort(L1) << 16);
    return (uint32_t)__bfloat16_as_ushort(h0) | ((uint32_t)__bfloat16_as_ushort(h1) << 16);
}
// fp16 hi/lo pair pack (GEMM activation path)
__device__ __forceinline__ uint32_t split2h(float v0, float v1, uint32_t& lo) {
    __half h0 = __float2half_rn(v0), h1 = __float2half_rn(v1);
    float l0 = v0 - __half2float(h0), l1 = v1 - __half2float(h1);
    __half L0 = __float2half_rn(l0), L1 = __float2half_rn(l1);
    lo = (uint32_t)__half_as_ushort(L0) | ((uint32_t)__half_as_ushort(L1) << 16);
    return (uint32_t)__half_as_ushort(h0) | ((uint32_t)__half_as_ushort(h1) << 16);
}

// ---------------------------------------------------------------------------
// Conversion kernels
// ---------------------------------------------------------------------------
__global__ __launch_bounds__(256) void split_x_h(const float* __restrict__ src,
                                                 __half* __restrict__ hi,
                                                 __half* __restrict__ lo, int n4)
{
    int i = blockIdx.x * 256 + threadIdx.x;
    if (i >= n4) return;
    float4 v = ((const float4*)src)[i];
    uint32_t h0, h1, l0, l1;
    h0 = split2h(v.x, v.y, l0);
    h1 = split2h(v.z, v.w, l1);
    ((uint2*)hi)[i] = make_uint2(h0, h1);
    ((uint2*)lo)[i] = make_uint2(l0, l1);
}

// W[K,N] fp32 -> transposed single fp16 [N,K]
__global__ __launch_bounds__(256) void split_wt_h(const float* __restrict__ W,
                                                  __half* __restrict__ T)
{
    __shared__ float tile[32][33];
    const int tx = threadIdx.x, ty = threadIdx.y;        // (32, 8)
    const int bn = blockIdx.x * 32, bk = blockIdx.y * 32;
#pragma unroll
    for (int j = 0; j < 32; j += 8)
        tile[ty + j][tx] = W[(size_t)(bk + ty + j) * DMODEL + bn + tx];
    __syncthreads();
#pragma unroll
    for (int j = 0; j < 32; j += 8)
        T[(size_t)(bn + ty + j) * DMODEL + bk + tx] = __float2half_rn(tile[tx][ty + j]);
}

// ---------------------------------------------------------------------------
// fp16 mma.sync GEMM, 2-product split: C = (Ah+Al)[M,K] * Bh[N,K]^T.
// CTA 128x128, BK=32, 8 warps (4m x 2n -> warp 32x64), 2-stage cp.async.
// Epilogue: fp32 out (Cf) or bf16 hi/lo with scale (Ch/Cl, attention feed).
// ---------------------------------------------------------------------------
#define TILE_B   (128 * 40 * 2)            // 10240 B per 128x32 fp16 tile
#define STAGE_B  (3 * TILE_B)              // Ah, Al, Bh
#define NSTAGE   (DMODEL / 32)             // 32

extern __shared__ char dyn_smem[];

__global__ __launch_bounds__(256, 2) void gemm_f16(
    const __half* __restrict__ Ah, const __half* __restrict__ Al,
    const __half* __restrict__ Bh,
    float* __restrict__ Cf, __nv_bfloat16* __restrict__ Ch,
    __nv_bfloat16* __restrict__ Cl, float scale)
{
    const uint32_t sb = smem_u32(dyn_smem);
    const int tid  = threadIdx.x;
    const int lane = tid & 31;
    const int wid  = tid >> 5;
    const int m0   = (wid & 3) * 32;
    const int n0   = (wid >> 2) * 64;
    const int row0 = blockIdx.y * 128;
    const int col0 = blockIdx.x * 128;

    const __half* srcs[3] = {Ah, Al, Bh};

    float acc[2][8][4];
#pragma unroll
    for (int a = 0; a < 2; a++)
#pragma unroll
        for (int b = 0; b < 8; b++)
#pragma unroll
            for (int d = 0; d < 4; d++) acc[a][b][d] = 0.f;

    const int a_row = lane & 15;
    const int a_col = 8 * (lane >> 4);
    const int b_row = (lane & 7) + 8 * (lane >> 4);
    const int b_col = 8 * ((lane >> 3) & 1);

    auto load_stage = [&](int s) {
        const uint32_t base = sb + (uint32_t)(s & 1) * STAGE_B;
        const int k0 = s * 32;
#pragma unroll
        for (int t = 0; t < 3; t++) {
            const uint32_t tb = base + (uint32_t)t * TILE_B;
            const int gr0 = (t < 2) ? row0 : col0;
#pragma unroll
            for (int i = 0; i < 2; i++) {
                int f  = tid + i * 256;
                int r  = f >> 2;
                int ch = f & 3;
                cp_async16(tb + (uint32_t)(r * 80 + ch * 16),
                           srcs[t] + (size_t)(gr0 + r) * DMODEL + k0 + ch * 8);
            }
        }
        CP_COMMIT();
    };

    load_stage(0);

    for (int s = 0; s < NSTAGE; s++) {
        if (s + 1 < NSTAGE) { load_stage(s + 1); CP_WAIT(1); }
        else                 { CP_WAIT(0); }
        __syncthreads();

        const uint32_t base = sb + (uint32_t)(s & 1) * STAGE_B;
        const uint32_t aHB = base, aLB = base + TILE_B, bHB = base + 2 * TILE_B;

#pragma unroll
        for (int kk = 0; kk < 32; kk += 16) {
            uint32_t ah[2][4], al[2][4];
#pragma unroll
            for (int mi = 0; mi < 2; mi++) {
                uint32_t off = (uint32_t)((m0 + mi * 16 + a_row) * 80 +
                                          (kk + a_col) * 2);
                ldsm_x4(ah[mi], aHB + off);
                ldsm_x4(al[mi], aLB + off);
            }
#pragma unroll
            for (int ng = 0; ng < 4; ng++) {
                uint32_t boff = (uint32_t)((n0 + ng * 16 + b_row) * 80 +
                                           (kk + b_col) * 2);
                uint32_t bh[4];
                ldsm_x4(bh, bHB + boff);
#pragma unroll
                for (int mi = 0; mi < 2; mi++) {
                    mma_f16(acc[mi][2 * ng],     ah[mi], bh[0], bh[1]);
                    mma_f16(acc[mi][2 * ng + 1], ah[mi], bh[2], bh[3]);
                    mma_f16(acc[mi][2 * ng],     al[mi], bh[0], bh[1]);
                    mma_f16(acc[mi][2 * ng + 1], al[mi], bh[2], bh[3]);
                }
            }
        }
        __syncthreads();
    }

#pragma unroll
    for (int mi = 0; mi < 2; mi++) {
        int r = row0 + m0 + mi * 16 + (lane >> 2);
#pragma unroll
        for (int nj = 0; nj < 8; nj++) {
            int c = col0 + n0 + nj * 8 + (lane & 3) * 2;
            float v0 = acc[mi][nj][0] * scale, v1 = acc[mi][nj][1] * scale;
            float v2 = acc[mi][nj][2] * scale, v3 = acc[mi][nj][3] * scale;
            if (Ch) {
                uint32_t lo0, lo1;
                uint32_t hi0 = split2(v0, v1, lo0);
                uint32_t hi1 = split2(v2, v3, lo1);
                *(uint32_t*)&Ch[(size_t)r * DMODEL + c]       = hi0;
                *(uint32_t*)&Cl[(size_t)r * DMODEL + c]       = lo0;
                *(uint32_t*)&Ch[(size_t)(r + 8) * DMODEL + c] = hi1;
                *(uint32_t*)&Cl[(size_t)(r + 8) * DMODEL + c] = lo1;
            } else {
                *(float2*)&Cf[(size_t)r * DMODEL + c]       = make_float2(v0, v1);
                *(float2*)&Cf[(size_t)(r + 8) * DMODEL + c] = make_float2(v2, v3);
            }
        }
    }
}

// ---------------------------------------------------------------------------
// FlashAttention-2 on mma.sync (validated R8 core, bf16 3-term).
// Epilogue now emits fp16 hi/lo Z for the fp16 out-projection.
// ---------------------------------------------------------------------------
#define ATT_QH   0u
#define ATT_QL   16384u
#define ATT_BUF  32768u
#define ATT_SMEM 98304u

__global__ __launch_bounds__(256, 2) void attn_tc()
{
    const uint32_t sb = smem_u32(dyn_smem);
    const int tid  = threadIdx.x;
    const int lane = tid & 31;
    const int wid  = tid >> 5;
    const int m0   = wid * 16;
    const int bh   = blockIdx.y;
    const int base = (bh >> 4) * T_SEQ;
    const int h64  = (bh & 15) * DH;
    const int qb   = ((int)gridDim.x - 1 - (int)blockIdx.x) * 128;
    const int ntiles = qb / 64 + 2;

#pragma unroll
    for (int i = 0; i < 4; i++) {
        int f = tid + 256 * i;
        int r = f >> 3, ch = f & 7;
        uint32_t off = SW128((uint32_t)(r * 128 + ch * 16));
        size_t g = (size_t)(base + qb + r) * DMODEL + h64 + ch * 8;
        cp_async16(sb + ATT_QH + off, &g_Qh[g]);
        cp_async16(sb + ATT_QL + off, &g_Ql[g]);
    }
    CP_COMMIT();

    auto load_kv = [&](int t) {
        const uint32_t bufb = sb + ATT_BUF + (uint32_t)(t & 1) * 32768u;
        const int kt = t * 64;
#pragma unroll
        for (int i = 0; i < 2; i++) {
            int f = tid + 256 * i;
            int r = f >> 3, ch = f & 7;
            uint32_t off = SW128((uint32_t)(r * 128 + ch * 16));
            size_t g = (size_t)(base + kt + r) * DMODEL + h64 + ch * 8;
            cp_async16(bufb + off,         &g_Kh[g]);
            cp_async16(bufb + 8192 + off,  &g_Kl[g]);
            cp_async16(bufb + 16384 + off, &g_Vh[g]);
            cp_async16(bufb + 24576 + off, &g_Vl[g]);
        }
        CP_COMMIT();
    };

    load_kv(0);

    const int a_row = lane & 15;
    const int a_col = 8 * (lane >> 4);
    const int b_row = (lane & 7) + 8 * (lane >> 4);
    const int b_col = 8 * ((lane >> 3) & 1);

    CP_WAIT(1);
    __syncthreads();
    uint32_t qh[4][4], ql[4][4];
#pragma unroll
    for (int ks = 0; ks < 4; ks++) {
        uint32_t off = SW128((uint32_t)((m0 + a_row) * 128 + (ks * 16 + a_col) * 2));
        ldsm_x4(qh[ks], sb + ATT_QH + off);
        ldsm_x4(ql[ks], sb + ATT_QL + off);
    }

    float o[8][4];
#pragma unroll
    for (int b = 0; b < 8; b++)
#pragma unroll
        for (int d = 0; d < 4; d++) o[b][d] = 0.f;
    float mrow[2] = {-1e30f, -1e30f};
    float lrow[2] = {0.f, 0.f};

    for (int t = 0; t < ntiles; t++) {
        if (t + 1 < ntiles) { load_kv(t + 1); CP_WAIT(1); }
        else                 { CP_WAIT(0); }
        __syncthreads();

        const uint32_t bufb = sb + ATT_BUF + (uint32_t)(t & 1) * 32768u;
        const uint32_t KHb = bufb, KLb = bufb + 8192;
        const uint32_t VHb = bufb + 16384, VLb = bufb + 24576;
        const int kt = t * 64;

        float s[8][4];
#pragma unroll
        for (int b = 0; b < 8; b++)
#pragma unroll
            for (int d = 0; d < 4; d++) s[b][d] = 0.f;

#pragma unroll
        for (int ks = 0; ks < 4; ks++) {
#pragma unroll
            for (int jp = 0; jp < 4; jp++) {
                uint32_t boff = SW128((uint32_t)((jp * 16 + b_row) * 128 +
                                                 (ks * 16 + b_col) * 2));
                uint32_t kh[4], kl[4];
                ldsm_x4(kh, KHb + boff);
                ldsm_x4(kl, KLb + boff);
                mma_bf16(s[2 * jp],     qh[ks], kh[0], kh[1]);
                mma_bf16(s[2 * jp + 1], qh[ks], kh[2], kh[3]);
                mma_bf16(s[2 * jp],     qh[ks], kl[0], kl[1]);
                mma_bf16(s[2 * jp + 1], qh[ks], kl[2], kl[3]);
                mma_bf16(s[2 * jp],     ql[ks], kh[0], kh[1]);
                mma_bf16(s[2 * jp + 1], ql[ks], kh[2], kh[3]);
            }
        }

        if (t >= ntiles - 2) {
            int rlo = qb + m0 + (lane >> 2);
#pragma unroll
            for (int j = 0; j < 8; j++) {
                int c0 = kt + j * 8 + (lane & 3) * 2;
                if (c0 > rlo)         s[j][0] = -1e30f;
                if (c0 + 1 > rlo)     s[j][1] = -1e30f;
                if (c0 > rlo + 8)     s[j][2] = -1e30f;
                if (c0 + 1 > rlo + 8) s[j][3] = -1e30f;
            }
        }

        {
            float mx0 = -1e30f, mx1 = -1e30f;
#pragma unroll
            for (int j = 0; j < 8; j++) {
                mx0 = fmaxf(mx0, fmaxf(s[j][0], s[j][1]));
                mx1 = fmaxf(mx1, fmaxf(s[j][2], s[j][3]));
            }
            mx0 = fmaxf(mx0, __shfl_xor_sync(0xffffffff, mx0, 1));
            mx0 = fmaxf(mx0, __shfl_xor_sync(0xffffffff, mx0, 2));
            mx1 = fmaxf(mx1, __shfl_xor_sync(0xffffffff, mx1, 1));
            mx1 = fmaxf(mx1, __shfl_xor_sync(0xffffffff, mx1, 2));
            float mn0 = fmaxf(mrow[0], mx0), mn1 = fmaxf(mrow[1], mx1);
            float c0 = ex2(mrow[0] - mn0),   c1 = ex2(mrow[1] - mn1);
            mrow[0] = mn0; mrow[1] = mn1;
            lrow[0] *= c0; lrow[1] *= c1;
#pragma unroll
            for (int j = 0; j < 8; j++) {
                o[j][0] *= c0; o[j][1] *= c0;
                o[j][2] *= c1; o[j][3] *= c1;
            }
            float sum0 = 0.f, sum1 = 0.f;
#pragma unroll
            for (int j = 0; j < 8; j++) {
                float p0 = ex2(s[j][0] - mn0);
                float p1 = ex2(s[j][1] - mn0);
                float p2 = ex2(s[j][2] - mn1);
                float p3 = ex2(s[j][3] - mn1);
                s[j][0] = p0; s[j][1] = p1;
                s[j][2] = p2; s[j][3] = p3;
                sum0 += p0 + p1; sum1 += p2 + p3;
            }
            lrow[0] += sum0; lrow[1] += sum1;
        }

#pragma unroll
        for (int ks = 0; ks < 4; ks++) {
            uint32_t ph[4], pl[4];
            ph[0] = split2(s[2 * ks][0],     s[2 * ks][1],     pl[0]);
            ph[1] = split2(s[2 * ks][2],     s[2 * ks][3],     pl[1]);
            ph[2] = split2(s[2 * ks + 1][0], s[2 * ks + 1][1], pl[2]);
            ph[3] = split2(s[2 * ks + 1][2], s[2 * ks + 1][3], pl[3]);
#pragma unroll
            for (int jp = 0; jp < 4; jp++) {
                uint32_t voff = SW128((uint32_t)((ks * 16 + a_row) * 128 +
                                                 (jp * 16 + a_col) * 2));
                uint32_t vh[4], vl[4];
                ldsm_x4_t(vh, VHb + voff);
                ldsm_x4_t(vl, VLb + voff);
                mma_bf16(o[2 * jp],     ph, vh[0], vh[1]);
                mma_bf16(o[2 * jp + 1], ph, vh[2], vh[3]);
                mma_bf16(o[2 * jp],     ph, vl[0], vl[1]);
                mma_bf16(o[2 * jp + 1], ph, vl[2], vl[3]);
                mma_bf16(o[2 * jp],     pl, vh[0], vh[1]);
                mma_bf16(o[2 * jp + 1], pl, vh[2], vh[3]);
            }
        }
        __syncthreads();
    }

    // ---- finalize: z = O/l, write fp16 hi/lo Z ----
    {
        float l0 = lrow[0], l1 = lrow[1];
        l0 += __shfl_xor_sync(0xffffffff, l0, 1);
        l0 += __shfl_xor_sync(0xffffffff, l0, 2);
        l1 += __shfl_xor_sync(0xffffffff, l1, 1);
        l1 += __shfl_xor_sync(0xffffffff, l1, 2);
        float inv0 = 1.f / l0, inv1 = 1.f / l1;
        size_t rlo = (size_t)(base + qb + m0 + (lane >> 2)) * DMODEL;
        size_t rhi = rlo + 8 * DMODEL;
#pragma unroll
        for (int j = 0; j < 8; j++) {
            int c = h64 + j * 8 + (lane & 3) * 2;
            uint32_t lo0, lo1;
            uint32_t hi0 = split2h(o[j][0] * inv0, o[j][1] * inv0, lo0);
            uint32_t hi1 = split2h(o[j][2] * inv1, o[j][3] * inv1, lo1);
            *(uint32_t*)&g_Zh[rlo + c] = hi0;
            *(uint32_t*)&g_Zl[rlo + c] = lo0;
            *(uint32_t*)&g_Zh[rhi + c] = hi1;
            *(uint32_t*)&g_Zl[rhi + c] = lo1;
        }
    }
}

// ---------------------------------------------------------------------------
extern "C" void kernel_launch(void* const* d_in, const int* in_sizes, int n_in,
                              void* d_out, int out_size)
{
    const float* x = (const float*)d_in[0];
    const float* W[4] = {(const float*)d_in[1], (const float*)d_in[2],
                         (const float*)d_in[3], (const float*)d_in[4]};
    float* out = (float*)d_out;

    __nv_bfloat16 *Qh, *Ql, *Kh, *Kl, *Vh, *Vl;
    __half *xh, *xl, *Zh, *Zl, *Wt;
    cudaGetSymbolAddress((void**)&Qh, g_Qh);   cudaGetSymbolAddress((void**)&Ql, g_Ql);
    cudaGetSymbolAddress((void**)&Kh, g_Kh);   cudaGetSymbolAddress((void**)&Kl, g_Kl);
    cudaGetSymbolAddress((void**)&Vh, g_Vh);   cudaGetSymbolAddress((void**)&Vl, g_Vl);
    cudaGetSymbolAddress((void**)&xh, g_xh);   cudaGetSymbolAddress((void**)&xl, g_xl);
    cudaGetSymbolAddress((void**)&Zh, g_Zh);   cudaGetSymbolAddress((void**)&Zl, g_Zl);
    cudaGetSymbolAddress((void**)&Wt, g_W);

    cudaFuncSetAttribute(gemm_f16, cudaFuncAttributeMaxDynamicSharedMemorySize,
                         2 * STAGE_B);
    cudaFuncSetAttribute(attn_tc, cudaFuncAttributeMaxDynamicSharedMemorySize,
                         ATT_SMEM);

    const size_t WSZ = (size_t)DMODEL * DMODEL;
    const int nx4 = MROWS * DMODEL / 4;
    dim3 tblk(32, 8), tgrd(DMODEL / 32, DMODEL / 32);

    split_x_h<<<(nx4 + 255) / 256, 256>>>(x, xh, xl, nx4);
    for (int w = 0; w < 4; w++)
        split_wt_h<<<tgrd, tblk>>>(W[w], Wt + w * WSZ);

    dim3 ggrid(DMODEL / 128, MROWS / 128);   // (8, 32)
    gemm_f16<<<ggrid, 256, 2 * STAGE_B>>>(xh, xl, Wt + 0 * WSZ, nullptr, Qh, Ql, QSCALE);
    gemm_f16<<<ggrid, 256, 2 * STAGE_B>>>(xh, xl, Wt + 1 * WSZ, nullptr, Kh, Kl, 1.0f);
    gemm_f16<<<ggrid, 256, 2 * STAGE_B>>>(xh, xl, Wt + 2 * WSZ, nullptr, Vh, Vl, 1.0f);

    attn_tc<<<dim3(T_SEQ / 128, NB * NH), 256, ATT_SMEM>>>();

    gemm_f16<<<ggrid, 256, 2 * STAGE_B>>>(Zh, Zl, Wt + 3 * WSZ, out, nullptr, nullptr, 1.0f);
}

// round 13
// speedup vs baseline: 2.8762x; 1.2665x over previous
#include <cuda_runtime.h>
#include <cuda_fp16.h>
#include <cstdint>

#define MROWS  4096   // B*T
#define DMODEL 1024
#define T_SEQ  2048
#define NB     2
#define NH     16
#define DH     64
#define QSCALE 0.1803368801111244f   // 0.125 * log2(e)

// ---------------- scratch (__device__ globals: allocation-free rule) --------
__device__ __half g_Qh[MROWS * DMODEL], g_Ql[MROWS * DMODEL];   // Q hi/lo (pre-scaled)
__device__ __half g_K [MROWS * DMODEL];                          // K single fp16
__device__ __half g_V [MROWS * DMODEL];                          // V single fp16
__device__ __half g_xh[MROWS * DMODEL], g_xl[MROWS * DMODEL];
__device__ __half g_Zh[MROWS * DMODEL], g_Zl[MROWS * DMODEL];
__device__ __half g_W[4][DMODEL * DMODEL];                       // transposed [N,K]

// ---------------------------------------------------------------------------
// PTX helpers (plain sm_103: cp.async, ldmatrix, mma.sync, ex2.approx)
// ---------------------------------------------------------------------------
__device__ __forceinline__ uint32_t smem_u32(const void* p) {
    uint32_t a;
    asm("{ .reg .u64 t; cvta.to.shared.u64 t, %1; cvt.u32.u64 %0, t; }"
        : "=r"(a) : "l"(p));
    return a;
}
__device__ __forceinline__ void cp_async16(uint32_t dst, const void* src) {
    asm volatile("cp.async.cg.shared.global [%0], [%1], 16;" :: "r"(dst), "l"(src));
}
#define CP_COMMIT() asm volatile("cp.async.commit_group;" ::: "memory")
#define CP_WAIT(n)  asm volatile("cp.async.wait_group %0;" :: "n"(n) : "memory")
#define SW128(off)  ((off) ^ (((off) >> 3) & 0x70))

__device__ __forceinline__ void ldsm_x4(uint32_t* r, uint32_t addr) {
    asm volatile("ldmatrix.sync.aligned.m8n8.x4.shared.b16 {%0,%1,%2,%3}, [%4];"
                 : "=r"(r[0]), "=r"(r[1]), "=r"(r[2]), "=r"(r[3]) : "r"(addr));
}
__device__ __forceinline__ void ldsm_x4_t(uint32_t* r, uint32_t addr) {
    asm volatile("ldmatrix.sync.aligned.m8n8.x4.trans.shared.b16 {%0,%1,%2,%3}, [%4];"
                 : "=r"(r[0]), "=r"(r[1]), "=r"(r[2]), "=r"(r[3]) : "r"(addr));
}
__device__ __forceinline__ void mma_f16(float* c, const uint32_t* a,
                                        uint32_t b0, uint32_t b1) {
    asm volatile(
        "mma.sync.aligned.m16n8k16.row.col.f32.f16.f16.f32 "
        "{%0,%1,%2,%3}, {%4,%5,%6,%7}, {%8,%9}, {%0,%1,%2,%3};"
        : "+f"(c[0]), "+f"(c[1]), "+f"(c[2]), "+f"(c[3])
        : "r"(a[0]), "r"(a[1]), "r"(a[2]), "r"(a[3]), "r"(b0), "r"(b1));
}
__device__ __forceinline__ float ex2(float x) {
    float r; asm("ex2.approx.f32 %0, %1;" : "=f"(r) : "f"(x)); return r;
}
__device__ __forceinline__ uint32_t pack_h2(float v0, float v1) {
    __half2 h = __floats2half2_rn(v0, v1);
    return *(uint32_t*)&h;
}
// fp16 hi/lo pair pack
__device__ __forceinline__ uint32_t split2h(float v0, float v1, uint32_t& lo) {
    __half h0 = __float2half_rn(v0), h1 = __float2half_rn(v1);
    float l0 = v0 - __half2float(h0), l1 = v1 - __half2float(h1);
    lo = pack_h2(l0, l1);
    uint32_t hi;
    __half2 hh = __halves2half2(h0, h1);
    hi = *(uint32_t*)&hh;
    return hi;
}

// ---------------------------------------------------------------------------
// Conversion kernels
// ---------------------------------------------------------------------------
__global__ __launch_bounds__(256) void split_x_h(const float* __restrict__ src,
                                                 __half* __restrict__ hi,
                                                 __half* __restrict__ lo, int n4)
{
    int i = blockIdx.x * 256 + threadIdx.x;
    if (i >= n4) return;
    float4 v = ((const float4*)src)[i];
    uint32_t h0, h1, l0, l1;
    h0 = split2h(v.x, v.y, l0);
    h1 = split2h(v.z, v.w, l1);
    ((uint2*)hi)[i] = make_uint2(h0, h1);
    ((uint2*)lo)[i] = make_uint2(l0, l1);
}

// W[K,N] fp32 -> transposed single fp16 [N,K]
__global__ __launch_bounds__(256) void split_wt_h(const float* __restrict__ W,
                                                  __half* __restrict__ T)
{
    __shared__ float tile[32][33];
    const int tx = threadIdx.x, ty = threadIdx.y;        // (32, 8)
    const int bn = blockIdx.x * 32, bk = blockIdx.y * 32;
#pragma unroll
    for (int j = 0; j < 32; j += 8)
        tile[ty + j][tx] = W[(size_t)(bk + ty + j) * DMODEL + bn + tx];
    __syncthreads();
#pragma unroll
    for (int j = 0; j < 32; j += 8)
        T[(size_t)(bn + ty + j) * DMODEL + bk + tx] = __float2half_rn(tile[tx][ty + j]);
}

// ---------------------------------------------------------------------------
// fp16 mma.sync GEMM, 2-product split: C = (Ah+Al)[M,K] * Bh[N,K]^T.
// CTA 128x128, BK=32, 8 warps (4m x 2n), 2-stage cp.async.
// Epilogue modes: Cf (fp32) | Ch+Cl (fp16 hi/lo) | Ch only (single fp16).
// ---------------------------------------------------------------------------
#define TILE_B   (128 * 40 * 2)            // 10240 B per 128x32 fp16 tile
#define STAGE_B  (3 * TILE_B)              // Ah, Al, Bh
#define NSTAGE   (DMODEL / 32)             // 32

extern __shared__ char dyn_smem[];

__global__ __launch_bounds__(256, 2) void gemm_f16(
    const __half* __restrict__ Ah, const __half* __restrict__ Al,
    const __half* __restrict__ Bh,
    float* __restrict__ Cf, __half* __restrict__ Ch,
    __half* __restrict__ Cl, float scale)
{
    const uint32_t sb = smem_u32(dyn_smem);
    const int tid  = threadIdx.x;
    const int lane = tid & 31;
    const int wid  = tid >> 5;
    const int m0   = (wid & 3) * 32;
    const int n0   = (wid >> 2) * 64;
    const int row0 = blockIdx.y * 128;
    const int col0 = blockIdx.x * 128;

    const __half* srcs[3] = {Ah, Al, Bh};

    float acc[2][8][4];
#pragma unroll
    for (int a = 0; a < 2; a++)
#pragma unroll
        for (int b = 0; b < 8; b++)
#pragma unroll
            for (int d = 0; d < 4; d++) acc[a][b][d] = 0.f;

    const int a_row = lane & 15;
    const int a_col = 8 * (lane >> 4);
    const int b_row = (lane & 7) + 8 * (lane >> 4);
    const int b_col = 8 * ((lane >> 3) & 1);

    auto load_stage = [&](int s) {
        const uint32_t base = sb + (uint32_t)(s & 1) * STAGE_B;
        const int k0 = s * 32;
#pragma unroll
        for (int t = 0; t < 3; t++) {
            const uint32_t tb = base + (uint32_t)t * TILE_B;
            const int gr0 = (t < 2) ? row0 : col0;
#pragma unroll
            for (int i = 0; i < 2; i++) {
                int f  = tid + i * 256;
                int r  = f >> 2;
                int ch = f & 3;
                cp_async16(tb + (uint32_t)(r * 80 + ch * 16),
                           srcs[t] + (size_t)(gr0 + r) * DMODEL + k0 + ch * 8);
            }
        }
        CP_COMMIT();
    };

    load_stage(0);

    for (int s = 0; s < NSTAGE; s++) {
        if (s + 1 < NSTAGE) { load_stage(s + 1); CP_WAIT(1); }
        else                 { CP_WAIT(0); }
        __syncthreads();

        const uint32_t base = sb + (uint32_t)(s & 1) * STAGE_B;
        const uint32_t aHB = base, aLB = base + TILE_B, bHB = base + 2 * TILE_B;

#pragma unroll
        for (int kk = 0; kk < 32; kk += 16) {
            uint32_t ah[2][4], al[2][4];
#pragma unroll
            for (int mi = 0; mi < 2; mi++) {
                uint32_t off = (uint32_t)((m0 + mi * 16 + a_row) * 80 +
                                          (kk + a_col) * 2);
                ldsm_x4(ah[mi], aHB + off);
                ldsm_x4(al[mi], aLB + off);
            }
#pragma unroll
            for (int ng = 0; ng < 4; ng++) {
                uint32_t boff = (uint32_t)((n0 + ng * 16 + b_row) * 80 +
                                           (kk + b_col) * 2);
                uint32_t bh[4];
                ldsm_x4(bh, bHB + boff);
#pragma unroll
                for (int mi = 0; mi < 2; mi++) {
                    mma_f16(acc[mi][2 * ng],     ah[mi], bh[0], bh[1]);
                    mma_f16(acc[mi][2 * ng + 1], ah[mi], bh[2], bh[3]);
                    mma_f16(acc[mi][2 * ng],     al[mi], bh[0], bh[1]);
                    mma_f16(acc[mi][2 * ng + 1], al[mi], bh[2], bh[3]);
                }
            }
        }
        __syncthreads();
    }

#pragma unroll
    for (int mi = 0; mi < 2; mi++) {
        int r = row0 + m0 + mi * 16 + (lane >> 2);
#pragma unroll
        for (int nj = 0; nj < 8; nj++) {
            int c = col0 + n0 + nj * 8 + (lane & 3) * 2;
            float v0 = acc[mi][nj][0] * scale, v1 = acc[mi][nj][1] * scale;
            float v2 = acc[mi][nj][2] * scale, v3 = acc[mi][nj][3] * scale;
            if (Cf) {
                *(float2*)&Cf[(size_t)r * DMODEL + c]       = make_float2(v0, v1);
                *(float2*)&Cf[(size_t)(r + 8) * DMODEL + c] = make_float2(v2, v3);
            } else if (Cl) {
                uint32_t lo0, lo1;
                uint32_t hi0 = split2h(v0, v1, lo0);
                uint32_t hi1 = split2h(v2, v3, lo1);
                *(uint32_t*)&Ch[(size_t)r * DMODEL + c]       = hi0;
                *(uint32_t*)&Cl[(size_t)r * DMODEL + c]       = lo0;
                *(uint32_t*)&Ch[(size_t)(r + 8) * DMODEL + c] = hi1;
                *(uint32_t*)&Cl[(size_t)(r + 8) * DMODEL + c] = lo1;
            } else {
                *(uint32_t*)&Ch[(size_t)r * DMODEL + c]       = pack_h2(v0, v1);
                *(uint32_t*)&Ch[(size_t)(r + 8) * DMODEL + c] = pack_h2(v2, v3);
            }
        }
    }
}

// ---------------------------------------------------------------------------
// FlashAttention-2 on fp16 mma.sync, causal.
// QK^T: 2-term (Q hi/lo x K single); P.V: 1-term (P single x V single).
// 256 threads (8 warps x m16), Bc=64, double-buffered K/V.
// SMEM: QH@0 (16K), QL@16K, 2 x {K 8K, V 8K} @32K -> 64KB total.
// ---------------------------------------------------------------------------
#define ATT_QH   0u
#define ATT_QL   16384u
#define ATT_BUF  32768u          // + (t&1)*16384; K@+0, V@+8192
#define ATT_SMEM 65536u

__global__ __launch_bounds__(256, 2) void attn_tc()
{
    const uint32_t sb = smem_u32(dyn_smem);
    const int tid  = threadIdx.x;
    const int lane = tid & 31;
    const int wid  = tid >> 5;
    const int m0   = wid * 16;
    const int bh   = blockIdx.y;
    const int base = (bh >> 4) * T_SEQ;
    const int h64  = (bh & 15) * DH;
    const int qb   = ((int)gridDim.x - 1 - (int)blockIdx.x) * 128;  // heavy first
    const int ntiles = qb / 64 + 2;

    // ---- load Q tile (hi/lo): 1024 chunks per array ----
#pragma unroll
    for (int i = 0; i < 4; i++) {
        int f = tid + 256 * i;
        int r = f >> 3, ch = f & 7;
        uint32_t off = SW128((uint32_t)(r * 128 + ch * 16));
        size_t g = (size_t)(base + qb + r) * DMODEL + h64 + ch * 8;
        cp_async16(sb + ATT_QH + off, &g_Qh[g]);
        cp_async16(sb + ATT_QL + off, &g_Ql[g]);
    }
    CP_COMMIT();

    auto load_kv = [&](int t) {
        const uint32_t bufb = sb + ATT_BUF + (uint32_t)(t & 1) * 16384u;
        const int kt = t * 64;
#pragma unroll
        for (int i = 0; i < 2; i++) {
            int f = tid + 256 * i;       // 512 chunks per 64x64 fp16 array
            int r = f >> 3, ch = f & 7;
            uint32_t off = SW128((uint32_t)(r * 128 + ch * 16));
            size_t g = (size_t)(base + kt + r) * DMODEL + h64 + ch * 8;
            cp_async16(bufb + off,        &g_K[g]);
            cp_async16(bufb + 8192 + off, &g_V[g]);
        }
        CP_COMMIT();
    };

    load_kv(0);

    const int a_row = lane & 15;
    const int a_col = 8 * (lane >> 4);
    const int b_row = (lane & 7) + 8 * (lane >> 4);
    const int b_col = 8 * ((lane >> 3) & 1);

    // ---- hoist Q fragments into registers ----
    CP_WAIT(1);
    __syncthreads();
    uint32_t qh[4][4], ql[4][4];
#pragma unroll
    for (int ks = 0; ks < 4; ks++) {
        uint32_t off = SW128((uint32_t)((m0 + a_row) * 128 + (ks * 16 + a_col) * 2));
        ldsm_x4(qh[ks], sb + ATT_QH + off);
        ldsm_x4(ql[ks], sb + ATT_QL + off);
    }

    float o[8][4];
#pragma unroll
    for (int b = 0; b < 8; b++)
#pragma unroll
        for (int d = 0; d < 4; d++) o[b][d] = 0.f;
    float mrow[2] = {-1e30f, -1e30f};
    float lrow[2] = {0.f, 0.f};

    for (int t = 0; t < ntiles; t++) {
        if (t + 1 < ntiles) { load_kv(t + 1); CP_WAIT(1); }
        else                 { CP_WAIT(0); }
        __syncthreads();

        const uint32_t bufb = sb + ATT_BUF + (uint32_t)(t & 1) * 16384u;
        const uint32_t Kb = bufb, Vb = bufb + 8192;
        const int kt = t * 64;

        // ---- S = Q K^T (2-term fp16) ----
        float s[8][4];
#pragma unroll
        for (int b = 0; b < 8; b++)
#pragma unroll
            for (int d = 0; d < 4; d++) s[b][d] = 0.f;

#pragma unroll
        for (int ks = 0; ks < 4; ks++) {
#pragma unroll
            for (int jp = 0; jp < 4; jp++) {
                uint32_t boff = SW128((uint32_t)((jp * 16 + b_row) * 128 +
                                                 (ks * 16 + b_col) * 2));
                uint32_t kh[4];
                ldsm_x4(kh, Kb + boff);
                mma_f16(s[2 * jp],     qh[ks], kh[0], kh[1]);
                mma_f16(s[2 * jp + 1], qh[ks], kh[2], kh[3]);
                mma_f16(s[2 * jp],     ql[ks], kh[0], kh[1]);
                mma_f16(s[2 * jp + 1], ql[ks], kh[2], kh[3]);
            }
        }

        // ---- causal mask (only the two diagonal-crossing tiles) ----
        if (t >= ntiles - 2) {
            int rlo = qb + m0 + (lane >> 2);
#pragma unroll
            for (int j = 0; j < 8; j++) {
                int c0 = kt + j * 8 + (lane & 3) * 2;
                if (c0 > rlo)         s[j][0] = -1e30f;
                if (c0 + 1 > rlo)     s[j][1] = -1e30f;
                if (c0 > rlo + 8)     s[j][2] = -1e30f;
                if (c0 + 1 > rlo + 8) s[j][3] = -1e30f;
            }
        }

        // ---- online softmax (log2 domain; Q pre-scaled) ----
        {
            float mx0 = -1e30f, mx1 = -1e30f;
#pragma unroll
            for (int j = 0; j < 8; j++) {
                mx0 = fmaxf(mx0, fmaxf(s[j][0], s[j][1]));
                mx1 = fmaxf(mx1, fmaxf(s[j][2], s[j][3]));
            }
            mx0 = fmaxf(mx0, __shfl_xor_sync(0xffffffff, mx0, 1));
            mx0 = fmaxf(mx0, __shfl_xor_sync(0xffffffff, mx0, 2));
            mx1 = fmaxf(mx1, __shfl_xor_sync(0xffffffff, mx1, 1));
            mx1 = fmaxf(mx1, __shfl_xor_sync(0xffffffff, mx1, 2));
            float mn0 = fmaxf(mrow[0], mx0), mn1 = fmaxf(mrow[1], mx1);
            float c0 = ex2(mrow[0] - mn0),   c1 = ex2(mrow[1] - mn1);
            mrow[0] = mn0; mrow[1] = mn1;
            lrow[0] *= c0; lrow[1] *= c1;
#pragma unroll
            for (int j = 0; j < 8; j++) {
                o[j][0] *= c0; o[j][1] *= c0;
                o[j][2] *= c1; o[j][3] *= c1;
            }
            float sum0 = 0.f, sum1 = 0.f;
#pragma unroll
            for (int j = 0; j < 8; j++) {
                float p0 = ex2(s[j][0] - mn0);
                float p1 = ex2(s[j][1] - mn0);
                float p2 = ex2(s[j][2] - mn1);
                float p3 = ex2(s[j][3] - mn1);
                s[j][0] = p0; s[j][1] = p1;
                s[j][2] = p2; s[j][3] = p3;
                sum0 += p0 + p1; sum1 += p2 + p3;
            }
            lrow[0] += sum0; lrow[1] += sum1;
        }

        // ---- O += P V (1-term: P single fp16, V single fp16) ----
#pragma unroll
        for (int ks = 0; ks < 4; ks++) {
            uint32_t ph[4];
            ph[0] = pack_h2(s[2 * ks][0],     s[2 * ks][1]);
            ph[1] = pack_h2(s[2 * ks][2],     s[2 * ks][3]);
            ph[2] = pack_h2(s[2 * ks + 1][0], s[2 * ks + 1][1]);
            ph[3] = pack_h2(s[2 * ks + 1][2], s[2 * ks + 1][3]);
#pragma unroll
            for (int jp = 0; jp < 4; jp++) {
                uint32_t voff = SW128((uint32_t)((ks * 16 + a_row) * 128 +
                                                 (jp * 16 + a_col) * 2));
                uint32_t vh[4];
                ldsm_x4_t(vh, Vb + voff);
                mma_f16(o[2 * jp],     ph, vh[0], vh[1]);
                mma_f16(o[2 * jp + 1], ph, vh[2], vh[3]);
            }
        }
        __syncthreads();
    }

    // ---- finalize: z = O/l, write fp16 hi/lo Z ----
    {
        float l0 = lrow[0], l1 = lrow[1];
        l0 += __shfl_xor_sync(0xffffffff, l0, 1);
        l0 += __shfl_xor_sync(0xffffffff, l0, 2);
        l1 += __shfl_xor_sync(0xffffffff, l1, 1);
        l1 += __shfl_xor_sync(0xffffffff, l1, 2);
        float inv0 = 1.f / l0, inv1 = 1.f / l1;
        size_t rlo = (size_t)(base + qb + m0 + (lane >> 2)) * DMODEL;
        size_t rhi = rlo + 8 * DMODEL;
#pragma unroll
        for (int j = 0; j < 8; j++) {
            int c = h64 + j * 8 + (lane & 3) * 2;
            uint32_t lo0, lo1;
            uint32_t hi0 = split2h(o[j][0] * inv0, o[j][1] * inv0, lo0);
            uint32_t hi1 = split2h(o[j][2] * inv1, o[j][3] * inv1, lo1);
            *(uint32_t*)&g_Zh[rlo + c] = hi0;
            *(uint32_t*)&g_Zl[rlo + c] = lo0;
            *(uint32_t*)&g_Zh[rhi + c] = hi1;
            *(uint32_t*)&g_Zl[rhi + c] = lo1;
        }
    }
}

// ---------------------------------------------------------------------------
extern "C" void kernel_launch(void* const* d_in, const int* in_sizes, int n_in,
                              void* d_out, int out_size)
{
    const float* x = (const float*)d_in[0];
    const float* W[4] = {(const float*)d_in[1], (const float*)d_in[2],
                         (const float*)d_in[3], (const float*)d_in[4]};
    float* out = (float*)d_out;

    __half *Qh, *Ql, *Kq, *Vq, *xh, *xl, *Zh, *Zl, *Wt;
    cudaGetSymbolAddress((void**)&Qh, g_Qh); cudaGetSymbolAddress((void**)&Ql, g_Ql);
    cudaGetSymbolAddress((void**)&Kq, g_K);  cudaGetSymbolAddress((void**)&Vq, g_V);
    cudaGetSymbolAddress((void**)&xh, g_xh); cudaGetSymbolAddress((void**)&xl, g_xl);
    cudaGetSymbolAddress((void**)&Zh, g_Zh); cudaGetSymbolAddress((void**)&Zl, g_Zl);
    cudaGetSymbolAddress((void**)&Wt, g_W);

    cudaFuncSetAttribute(gemm_f16, cudaFuncAttributeMaxDynamicSharedMemorySize,
                         2 * STAGE_B);
    cudaFuncSetAttribute(attn_tc, cudaFuncAttributeMaxDynamicSharedMemorySize,
                         ATT_SMEM);

    const size_t WSZ = (size_t)DMODEL * DMODEL;
    const int nx4 = MROWS * DMODEL / 4;
    dim3 tblk(32, 8), tgrd(DMODEL / 32, DMODEL / 32);

    split_x_h<<<(nx4 + 255) / 256, 256>>>(x, xh, xl, nx4);
    for (int w = 0; w < 4; w++)
        split_wt_h<<<tgrd, tblk>>>(W[w], Wt + w * WSZ);

    dim3 ggrid(DMODEL / 128, MROWS / 128);   // (8, 32)
    gemm_f16<<<ggrid, 256, 2 * STAGE_B>>>(xh, xl, Wt + 0 * WSZ, nullptr, Qh, Ql, QSCALE);
    gemm_f16<<<ggrid, 256, 2 * STAGE_B>>>(xh, xl, Wt + 1 * WSZ, nullptr, Kq, nullptr, 1.0f);
    gemm_f16<<<ggrid, 256, 2 * STAGE_B>>>(xh, xl, Wt + 2 * WSZ, nullptr, Vq, nullptr, 1.0f);

    attn_tc<<<dim3(T_SEQ / 128, NB * NH), 256, ATT_SMEM>>>();

    gemm_f16<<<ggrid, 256, 2 * STAGE_B>>>(Zh, Zl, Wt + 3 * WSZ, out, nullptr, nullptr, 1.0f);
}

// round 14
// speedup vs baseline: 3.8934x; 1.3536x over previous
#include <cuda_runtime.h>
#include <cuda_fp16.h>
#include <cstdint>

#define MROWS  4096   // B*T
#define DMODEL 1024
#define T_SEQ  2048
#define NB     2
#define NH     16
#define DH     64
#define QSCALE 0.1803368801111244f   // 0.125 * log2(e)

// ---------------- scratch (__device__ globals: allocation-free rule) --------
__device__ __half g_Qh[MROWS * DMODEL], g_Ql[MROWS * DMODEL];   // Q hi/lo (pre-scaled)
__device__ __half g_K [MROWS * DMODEL];                          // K single fp16
__device__ __half g_V [MROWS * DMODEL];                          // V single fp16
__device__ __half g_x [MROWS * DMODEL];                          // x single fp16
__device__ __half g_Z [MROWS * DMODEL];                          // Z single fp16
__device__ __half g_W[4][DMODEL * DMODEL];                       // transposed [N,K]

// ---------------------------------------------------------------------------
// PTX helpers (plain sm_103: cp.async, ldmatrix, mma.sync, ex2.approx)
// ---------------------------------------------------------------------------
__device__ __forceinline__ uint32_t smem_u32(const void* p) {
    uint32_t a;
    asm("{ .reg .u64 t; cvta.to.shared.u64 t, %1; cvt.u32.u64 %0, t; }"
        : "=r"(a) : "l"(p));
    return a;
}
__device__ __forceinline__ void cp_async16(uint32_t dst, const void* src) {
    asm volatile("cp.async.cg.shared.global [%0], [%1], 16;" :: "r"(dst), "l"(src));
}
#define CP_COMMIT() asm volatile("cp.async.commit_group;" ::: "memory")
#define CP_WAIT(n)  asm volatile("cp.async.wait_group %0;" :: "n"(n) : "memory")
#define SW128(off)  ((off) ^ (((off) >> 3) & 0x70))

__device__ __forceinline__ void ldsm_x4(uint32_t* r, uint32_t addr) {
    asm volatile("ldmatrix.sync.aligned.m8n8.x4.shared.b16 {%0,%1,%2,%3}, [%4];"
                 : "=r"(r[0]), "=r"(r[1]), "=r"(r[2]), "=r"(r[3]) : "r"(addr));
}
__device__ __forceinline__ void ldsm_x4_t(uint32_t* r, uint32_t addr) {
    asm volatile("ldmatrix.sync.aligned.m8n8.x4.trans.shared.b16 {%0,%1,%2,%3}, [%4];"
                 : "=r"(r[0]), "=r"(r[1]), "=r"(r[2]), "=r"(r[3]) : "r"(addr));
}
__device__ __forceinline__ void mma_f16(float* c, const uint32_t* a,
                                        uint32_t b0, uint32_t b1) {
    asm volatile(
        "mma.sync.aligned.m16n8k16.row.col.f32.f16.f16.f32 "
        "{%0,%1,%2,%3}, {%4,%5,%6,%7}, {%8,%9}, {%0,%1,%2,%3};"
        : "+f"(c[0]), "+f"(c[1]), "+f"(c[2]), "+f"(c[3])
        : "r"(a[0]), "r"(a[1]), "r"(a[2]), "r"(a[3]), "r"(b0), "r"(b1));
}
__device__ __forceinline__ float ex2(float x) {
    float r; asm("ex2.approx.f32 %0, %1;" : "=f"(r) : "f"(x)); return r;
}
__device__ __forceinline__ uint32_t pack_h2(float v0, float v1) {
    __half2 h = __floats2half2_rn(v0, v1);
    return *(uint32_t*)&h;
}
__device__ __forceinline__ uint32_t split2h(float v0, float v1, uint32_t& lo) {
    __half h0 = __float2half_rn(v0), h1 = __float2half_rn(v1);
    float l0 = v0 - __half2float(h0), l1 = v1 - __half2float(h1);
    lo = pack_h2(l0, l1);
    __half2 hh = __halves2half2(h0, h1);
    return *(uint32_t*)&hh;
}

// ---------------------------------------------------------------------------
// Conversion kernels
// ---------------------------------------------------------------------------
__global__ __launch_bounds__(256) void cvt_x(const float* __restrict__ src,
                                             __half* __restrict__ dst, int n4)
{
    int i = blockIdx.x * 256 + threadIdx.x;
    if (i >= n4) return;
    float4 v = ((const float4*)src)[i];
    ((uint2*)dst)[i] = make_uint2(pack_h2(v.x, v.y), pack_h2(v.z, v.w));
}

// W[K,N] fp32 -> transposed single fp16 [N,K]
__global__ __launch_bounds__(256) void split_wt_h(const float* __restrict__ W,
                                                  __half* __restrict__ T)
{
    __shared__ float tile[32][33];
    const int tx = threadIdx.x, ty = threadIdx.y;        // (32, 8)
    const int bn = blockIdx.x * 32, bk = blockIdx.y * 32;
#pragma unroll
    for (int j = 0; j < 32; j += 8)
        tile[ty + j][tx] = W[(size_t)(bk + ty + j) * DMODEL + bn + tx];
    __syncthreads();
#pragma unroll
    for (int j = 0; j < 32; j += 8)
        T[(size_t)(bn + ty + j) * DMODEL + bk + tx] = __float2half_rn(tile[tx][ty + j]);
}

// ---------------------------------------------------------------------------
// fp16 mma.sync GEMM, single-product: C = A[M,K] * B[N,K]^T.
// CTA 128x128, BK=32, 8 warps (4m x 2n), 2-stage cp.async.
// Epilogue modes: Cf (fp32) | Ch+Cl (fp16 hi/lo, for Q) | Ch only (single).
// ---------------------------------------------------------------------------
#define TILE_B   (128 * 40 * 2)            // 10240 B per 128x32 fp16 tile
#define STAGE_B  (2 * TILE_B)              // A, B
#define NSTAGE   (DMODEL / 32)             // 32

extern __shared__ char dyn_smem[];

__global__ __launch_bounds__(256, 2) void gemm_f16(
    const __half* __restrict__ A, const __half* __restrict__ B,
    float* __restrict__ Cf, __half* __restrict__ Ch,
    __half* __restrict__ Cl, float scale)
{
    const uint32_t sb = smem_u32(dyn_smem);
    const int tid  = threadIdx.x;
    const int lane = tid & 31;
    const int wid  = tid >> 5;
    const int m0   = (wid & 3) * 32;
    const int n0   = (wid >> 2) * 64;
    const int row0 = blockIdx.y * 128;
    const int col0 = blockIdx.x * 128;

    const __half* srcs[2] = {A, B};

    float acc[2][8][4];
#pragma unroll
    for (int a = 0; a < 2; a++)
#pragma unroll
        for (int b = 0; b < 8; b++)
#pragma unroll
            for (int d = 0; d < 4; d++) acc[a][b][d] = 0.f;

    const int a_row = lane & 15;
    const int a_col = 8 * (lane >> 4);
    const int b_row = (lane & 7) + 8 * (lane >> 4);
    const int b_col = 8 * ((lane >> 3) & 1);

    auto load_stage = [&](int s) {
        const uint32_t base = sb + (uint32_t)(s & 1) * STAGE_B;
        const int k0 = s * 32;
#pragma unroll
        for (int t = 0; t < 2; t++) {
            const uint32_t tb = base + (uint32_t)t * TILE_B;
            const int gr0 = (t < 1) ? row0 : col0;
#pragma unroll
            for (int i = 0; i < 2; i++) {
                int f  = tid + i * 256;
                int r  = f >> 2;
                int ch = f & 3;
                cp_async16(tb + (uint32_t)(r * 80 + ch * 16),
                           srcs[t] + (size_t)(gr0 + r) * DMODEL + k0 + ch * 8);
            }
        }
        CP_COMMIT();
    };

    load_stage(0);

    for (int s = 0; s < NSTAGE; s++) {
        if (s + 1 < NSTAGE) { load_stage(s + 1); CP_WAIT(1); }
        else                 { CP_WAIT(0); }
        __syncthreads();

        const uint32_t base = sb + (uint32_t)(s & 1) * STAGE_B;
        const uint32_t aB = base, bB = base + TILE_B;

#pragma unroll
        for (int kk = 0; kk < 32; kk += 16) {
            uint32_t af[2][4];
#pragma unroll
            for (int mi = 0; mi < 2; mi++) {
                uint32_t off = (uint32_t)((m0 + mi * 16 + a_row) * 80 +
                                          (kk + a_col) * 2);
                ldsm_x4(af[mi], aB + off);
            }
#pragma unroll
            for (int ng = 0; ng < 4; ng++) {
                uint32_t boff = (uint32_t)((n0 + ng * 16 + b_row) * 80 +
                                           (kk + b_col) * 2);
                uint32_t bf[4];
                ldsm_x4(bf, bB + boff);
#pragma unroll
                for (int mi = 0; mi < 2; mi++) {
                    mma_f16(acc[mi][2 * ng],     af[mi], bf[0], bf[1]);
                    mma_f16(acc[mi][2 * ng + 1], af[mi], bf[2], bf[3]);
                }
            }
        }
        __syncthreads();
    }

#pragma unroll
    for (int mi = 0; mi < 2; mi++) {
        int r = row0 + m0 + mi * 16 + (lane >> 2);
#pragma unroll
        for (int nj = 0; nj < 8; nj++) {
            int c = col0 + n0 + nj * 8 + (lane & 3) * 2;
            float v0 = acc[mi][nj][0] * scale, v1 = acc[mi][nj][1] * scale;
            float v2 = acc[mi][nj][2] * scale, v3 = acc[mi][nj][3] * scale;
            if (Cf) {
                *(float2*)&Cf[(size_t)r * DMODEL + c]       = make_float2(v0, v1);
                *(float2*)&Cf[(size_t)(r + 8) * DMODEL + c] = make_float2(v2, v3);
            } else if (Cl) {
                uint32_t lo0, lo1;
                uint32_t hi0 = split2h(v0, v1, lo0);
                uint32_t hi1 = split2h(v2, v3, lo1);
                *(uint32_t*)&Ch[(size_t)r * DMODEL + c]       = hi0;
                *(uint32_t*)&Cl[(size_t)r * DMODEL + c]       = lo0;
                *(uint32_t*)&Ch[(size_t)(r + 8) * DMODEL + c] = hi1;
                *(uint32_t*)&Cl[(size_t)(r + 8) * DMODEL + c] = lo1;
            } else {
                *(uint32_t*)&Ch[(size_t)r * DMODEL + c]       = pack_h2(v0, v1);
                *(uint32_t*)&Ch[(size_t)(r + 8) * DMODEL + c] = pack_h2(v2, v3);
            }
        }
    }
}

// ---------------------------------------------------------------------------
// FlashAttention-2 on fp16 mma.sync, causal (unchanged from R12 WIN except
// Z epilogue -> single fp16).
// QK^T: 2-term (Q hi/lo x K single); P.V: 1-term.
// ---------------------------------------------------------------------------
#define ATT_QH   0u
#define ATT_QL   16384u
#define ATT_BUF  32768u          // + (t&1)*16384; K@+0, V@+8192
#define ATT_SMEM 65536u

__global__ __launch_bounds__(256, 2) void attn_tc()
{
    const uint32_t sb = smem_u32(dyn_smem);
    const int tid  = threadIdx.x;
    const int lane = tid & 31;
    const int wid  = tid >> 5;
    const int m0   = wid * 16;
    const int bh   = blockIdx.y;
    const int base = (bh >> 4) * T_SEQ;
    const int h64  = (bh & 15) * DH;
    const int qb   = ((int)gridDim.x - 1 - (int)blockIdx.x) * 128;  // heavy first
    const int ntiles = qb / 64 + 2;

    // ---- load Q tile (hi/lo) ----
#pragma unroll
    for (int i = 0; i < 4; i++) {
        int f = tid + 256 * i;
        int r = f >> 3, ch = f & 7;
        uint32_t off = SW128((uint32_t)(r * 128 + ch * 16));
        size_t g = (size_t)(base + qb + r) * DMODEL + h64 + ch * 8;
        cp_async16(sb + ATT_QH + off, &g_Qh[g]);
        cp_async16(sb + ATT_QL + off, &g_Ql[g]);
    }
    CP_COMMIT();

    auto load_kv = [&](int t) {
        const uint32_t bufb = sb + ATT_BUF + (uint32_t)(t & 1) * 16384u;
        const int kt = t * 64;
#pragma unroll
        for (int i = 0; i < 2; i++) {
            int f = tid + 256 * i;
            int r = f >> 3, ch = f & 7;
            uint32_t off = SW128((uint32_t)(r * 128 + ch * 16));
            size_t g = (size_t)(base + kt + r) * DMODEL + h64 + ch * 8;
            cp_async16(bufb + off,        &g_K[g]);
            cp_async16(bufb + 8192 + off, &g_V[g]);
        }
        CP_COMMIT();
    };

    load_kv(0);

    const int a_row = lane & 15;
    const int a_col = 8 * (lane >> 4);
    const int b_row = (lane & 7) + 8 * (lane >> 4);
    const int b_col = 8 * ((lane >> 3) & 1);

    // ---- hoist Q fragments into registers ----
    CP_WAIT(1);
    __syncthreads();
    uint32_t qh[4][4], ql[4][4];
#pragma unroll
    for (int ks = 0; ks < 4; ks++) {
        uint32_t off = SW128((uint32_t)((m0 + a_row) * 128 + (ks * 16 + a_col) * 2));
        ldsm_x4(qh[ks], sb + ATT_QH + off);
        ldsm_x4(ql[ks], sb + ATT_QL + off);
    }

    float o[8][4];
#pragma unroll
    for (int b = 0; b < 8; b++)
#pragma unroll
        for (int d = 0; d < 4; d++) o[b][d] = 0.f;
    float mrow[2] = {-1e30f, -1e30f};
    float lrow[2] = {0.f, 0.f};

    for (int t = 0; t < ntiles; t++) {
        if (t + 1 < ntiles) { load_kv(t + 1); CP_WAIT(1); }
        else                 { CP_WAIT(0); }
        __syncthreads();

        const uint32_t bufb = sb + ATT_BUF + (uint32_t)(t & 1) * 16384u;
        const uint32_t Kb = bufb, Vb = bufb + 8192;
        const int kt = t * 64;

        // ---- S = Q K^T (2-term fp16) ----
        float s[8][4];
#pragma unroll
        for (int b = 0; b < 8; b++)
#pragma unroll
            for (int d = 0; d < 4; d++) s[b][d] = 0.f;

#pragma unroll
        for (int ks = 0; ks < 4; ks++) {
#pragma unroll
            for (int jp = 0; jp < 4; jp++) {
                uint32_t boff = SW128((uint32_t)((jp * 16 + b_row) * 128 +
                                                 (ks * 16 + b_col) * 2));
                uint32_t kh[4];
                ldsm_x4(kh, Kb + boff);
                mma_f16(s[2 * jp],     qh[ks], kh[0], kh[1]);
                mma_f16(s[2 * jp + 1], qh[ks], kh[2], kh[3]);
                mma_f16(s[2 * jp],     ql[ks], kh[0], kh[1]);
                mma_f16(s[2 * jp + 1], ql[ks], kh[2], kh[3]);
            }
        }

        // ---- causal mask (only the two diagonal-crossing tiles) ----
        if (t >= ntiles - 2) {
            int rlo = qb + m0 + (lane >> 2);
#pragma unroll
            for (int j = 0; j < 8; j++) {
                int c0 = kt + j * 8 + (lane & 3) * 2;
                if (c0 > rlo)         s[j][0] = -1e30f;
                if (c0 + 1 > rlo)     s[j][1] = -1e30f;
                if (c0 > rlo + 8)     s[j][2] = -1e30f;
                if (c0 + 1 > rlo + 8) s[j][3] = -1e30f;
            }
        }

        // ---- online softmax (log2 domain; Q pre-scaled) ----
        {
            float mx0 = -1e30f, mx1 = -1e30f;
#pragma unroll
            for (int j = 0; j < 8; j++) {
                mx0 = fmaxf(mx0, fmaxf(s[j][0], s[j][1]));
                mx1 = fmaxf(mx1, fmaxf(s[j][2], s[j][3]));
            }
            mx0 = fmaxf(mx0, __shfl_xor_sync(0xffffffff, mx0, 1));
            mx0 = fmaxf(mx0, __shfl_xor_sync(0xffffffff, mx0, 2));
            mx1 = fmaxf(mx1, __shfl_xor_sync(0xffffffff, mx1, 1));
            mx1 = fmaxf(mx1, __shfl_xor_sync(0xffffffff, mx1, 2));
            float mn0 = fmaxf(mrow[0], mx0), mn1 = fmaxf(mrow[1], mx1);
            float c0 = ex2(mrow[0] - mn0),   c1 = ex2(mrow[1] - mn1);
            mrow[0] = mn0; mrow[1] = mn1;
            lrow[0] *= c0; lrow[1] *= c1;
#pragma unroll
            for (int j = 0; j < 8; j++) {
                o[j][0] *= c0; o[j][1] *= c0;
                o[j][2] *= c1; o[j][3] *= c1;
            }
            float sum0 = 0.f, sum1 = 0.f;
#pragma unroll
            for (int j = 0; j < 8; j++) {
                float p0 = ex2(s[j][0] - mn0);
                float p1 = ex2(s[j][1] - mn0);
                float p2 = ex2(s[j][2] - mn1);
                float p3 = ex2(s[j][3] - mn1);
                s[j][0] = p0; s[j][1] = p1;
                s[j][2] = p2; s[j][3] = p3;
                sum0 += p0 + p1; sum1 += p2 + p3;
            }
            lrow[0] += sum0; lrow[1] += sum1;
        }

        // ---- O += P V (1-term) ----
#pragma unroll
        for (int ks = 0; ks < 4; ks++) {
            uint32_t ph[4];
            ph[0] = pack_h2(s[2 * ks][0],     s[2 * ks][1]);
            ph[1] = pack_h2(s[2 * ks][2],     s[2 * ks][3]);
            ph[2] = pack_h2(s[2 * ks + 1][0], s[2 * ks + 1][1]);
            ph[3] = pack_h2(s[2 * ks + 1][2], s[2 * ks + 1][3]);
#pragma unroll
            for (int jp = 0; jp < 4; jp++) {
                uint32_t voff = SW128((uint32_t)((ks * 16 + a_row) * 128 +
                                                 (jp * 16 + a_col) * 2));
                uint32_t vh[4];
                ldsm_x4_t(vh, Vb + voff);
                mma_f16(o[2 * jp],     ph, vh[0], vh[1]);
                mma_f16(o[2 * jp + 1], ph, vh[2], vh[3]);
            }
        }
        __syncthreads();
    }

    // ---- finalize: z = O/l, write single fp16 Z ----
    {
        float l0 = lrow[0], l1 = lrow[1];
        l0 += __shfl_xor_sync(0xffffffff, l0, 1);
        l0 += __shfl_xor_sync(0xffffffff, l0, 2);
        l1 += __shfl_xor_sync(0xffffffff, l1, 1);
        l1 += __shfl_xor_sync(0xffffffff, l1, 2);
        float inv0 = 1.f / l0, inv1 = 1.f / l1;
        size_t rlo = (size_t)(base + qb + m0 + (lane >> 2)) * DMODEL;
        size_t rhi = rlo + 8 * DMODEL;
#pragma unroll
        for (int j = 0; j < 8; j++) {
            int c = h64 + j * 8 + (lane & 3) * 2;
            *(uint32_t*)&g_Z[rlo + c] = pack_h2(o[j][0] * inv0, o[j][1] * inv0);
            *(uint32_t*)&g_Z[rhi + c] = pack_h2(o[j][2] * inv1, o[j][3] * inv1);
        }
    }
}

// ---------------------------------------------------------------------------
extern "C" void kernel_launch(void* const* d_in, const int* in_sizes, int n_in,
                              void* d_out, int out_size)
{
    const float* x = (const float*)d_in[0];
    const float* W[4] = {(const float*)d_in[1], (const float*)d_in[2],
                         (const float*)d_in[3], (const float*)d_in[4]};
    float* out = (float*)d_out;

    __half *Qh, *Ql, *Kq, *Vq, *xq, *Zq, *Wt;
    cudaGetSymbolAddress((void**)&Qh, g_Qh); cudaGetSymbolAddress((void**)&Ql, g_Ql);
    cudaGetSymbolAddress((void**)&Kq, g_K);  cudaGetSymbolAddress((void**)&Vq, g_V);
    cudaGetSymbolAddress((void**)&xq, g_x);  cudaGetSymbolAddress((void**)&Zq, g_Z);
    cudaGetSymbolAddress((void**)&Wt, g_W);

    cudaFuncSetAttribute(gemm_f16, cudaFuncAttributeMaxDynamicSharedMemorySize,
                         2 * STAGE_B);
    cudaFuncSetAttribute(attn_tc, cudaFuncAttributeMaxDynamicSharedMemorySize,
                         ATT_SMEM);

    const size_t WSZ = (size_t)DMODEL * DMODEL;
    const int nx4 = MROWS * DMODEL / 4;
    dim3 tblk(32, 8), tgrd(DMODEL / 32, DMODEL / 32);

    cvt_x<<<(nx4 + 255) / 256, 256>>>(x, xq, nx4);
    for (int w = 0; w < 4; w++)
        split_wt_h<<<tgrd, tblk>>>(W[w], Wt + w * WSZ);

    dim3 ggrid(DMODEL / 128, MROWS / 128);   // (8, 32)
    gemm_f16<<<ggrid, 256, 2 * STAGE_B>>>(xq, Wt + 0 * WSZ, nullptr, Qh, Ql, QSCALE);
    gemm_f16<<<ggrid, 256, 2 * STAGE_B>>>(xq, Wt + 1 * WSZ, nullptr, Kq, nullptr, 1.0f);
    gemm_f16<<<ggrid, 256, 2 * STAGE_B>>>(xq, Wt + 2 * WSZ, nullptr, Vq, nullptr, 1.0f);

    attn_tc<<<dim3(T_SEQ / 128, NB * NH), 256, ATT_SMEM>>>();

    gemm_f16<<<ggrid, 256, 2 * STAGE_B>>>(Zq, Wt + 3 * WSZ, out, nullptr, nullptr, 1.0f);
}

// round 15
// speedup vs baseline: 4.3158x; 1.1085x over previous
#include <cuda_runtime.h>
#include <cuda_fp16.h>
#include <cstdint>

#define MROWS  4096   // B*T
#define DMODEL 1024
#define T_SEQ  2048
#define NB     2
#define NH     16
#define DH     64
#define QSCALE 0.1803368801111244f   // 0.125 * log2(e)

// ---------------- scratch (__device__ globals: allocation-free rule) --------
__device__ __half g_Q [MROWS * DMODEL];                          // Q single (pre-scaled)
__device__ __half g_K [MROWS * DMODEL];                          // K single fp16
__device__ __half g_V [MROWS * DMODEL];                          // V single fp16
__device__ __half g_x [MROWS * DMODEL];                          // x single fp16
__device__ __half g_Z [MROWS * DMODEL];                          // Z single fp16
__device__ __half g_W[4][DMODEL * DMODEL];                       // transposed [N,K]

// ---------------------------------------------------------------------------
// PTX helpers (plain sm_103: cp.async, ldmatrix, mma.sync, ex2.approx)
// ---------------------------------------------------------------------------
__device__ __forceinline__ uint32_t smem_u32(const void* p) {
    uint32_t a;
    asm("{ .reg .u64 t; cvta.to.shared.u64 t, %1; cvt.u32.u64 %0, t; }"
        : "=r"(a) : "l"(p));
    return a;
}
__device__ __forceinline__ void cp_async16(uint32_t dst, const void* src) {
    asm volatile("cp.async.cg.shared.global [%0], [%1], 16;" :: "r"(dst), "l"(src));
}
#define CP_COMMIT() asm volatile("cp.async.commit_group;" ::: "memory")
#define CP_WAIT(n)  asm volatile("cp.async.wait_group %0;" :: "n"(n) : "memory")
#define SW128(off)  ((off) ^ (((off) >> 3) & 0x70))

__device__ __forceinline__ void ldsm_x4(uint32_t* r, uint32_t addr) {
    asm volatile("ldmatrix.sync.aligned.m8n8.x4.shared.b16 {%0,%1,%2,%3}, [%4];"
                 : "=r"(r[0]), "=r"(r[1]), "=r"(r[2]), "=r"(r[3]) : "r"(addr));
}
__device__ __forceinline__ void ldsm_x4_t(uint32_t* r, uint32_t addr) {
    asm volatile("ldmatrix.sync.aligned.m8n8.x4.trans.shared.b16 {%0,%1,%2,%3}, [%4];"
                 : "=r"(r[0]), "=r"(r[1]), "=r"(r[2]), "=r"(r[3]) : "r"(addr));
}
__device__ __forceinline__ void mma_f16(float* c, const uint32_t* a,
                                        uint32_t b0, uint32_t b1) {
    asm volatile(
        "mma.sync.aligned.m16n8k16.row.col.f32.f16.f16.f32 "
        "{%0,%1,%2,%3}, {%4,%5,%6,%7}, {%8,%9}, {%0,%1,%2,%3};"
        : "+f"(c[0]), "+f"(c[1]), "+f"(c[2]), "+f"(c[3])
        : "r"(a[0]), "r"(a[1]), "r"(a[2]), "r"(a[3]), "r"(b0), "r"(b1));
}
__device__ __forceinline__ float ex2(float x) {
    float r; asm("ex2.approx.f32 %0, %1;" : "=f"(r) : "f"(x)); return r;
}
__device__ __forceinline__ uint32_t pack_h2(float v0, float v1) {
    __half2 h = __floats2half2_rn(v0, v1);
    return *(uint32_t*)&h;
}

// ---------------------------------------------------------------------------
// Conversion kernels
// ---------------------------------------------------------------------------
__global__ __launch_bounds__(256) void cvt_x(const float* __restrict__ src,
                                             __half* __restrict__ dst, int n4)
{
    int i = blockIdx.x * 256 + threadIdx.x;
    if (i >= n4) return;
    float4 v = ((const float4*)src)[i];
    ((uint2*)dst)[i] = make_uint2(pack_h2(v.x, v.y), pack_h2(v.z, v.w));
}

// All 4 weights in one launch: W[K,N] fp32 -> transposed fp16 [N,K], z = which W
__global__ __launch_bounds__(256) void split_wt_h4(
    const float* __restrict__ W0, const float* __restrict__ W1,
    const float* __restrict__ W2, const float* __restrict__ W3,
    __half* __restrict__ T)
{
    __shared__ float tile[32][33];
    const float* Ws[4] = {W0, W1, W2, W3};
    const float* W = Ws[blockIdx.z];
    __half* Tz = T + (size_t)blockIdx.z * DMODEL * DMODEL;
    const int tx = threadIdx.x, ty = threadIdx.y;        // (32, 8)
    const int bn = blockIdx.x * 32, bk = blockIdx.y * 32;
#pragma unroll
    for (int j = 0; j < 32; j += 8)
        tile[ty + j][tx] = W[(size_t)(bk + ty + j) * DMODEL + bn + tx];
    __syncthreads();
#pragma unroll
    for (int j = 0; j < 32; j += 8)
        Tz[(size_t)(bn + ty + j) * DMODEL + bk + tx] = __float2half_rn(tile[tx][ty + j]);
}

// ---------------------------------------------------------------------------
// fp16 mma.sync GEMM, single-product: C = A[M,K] * B[N,K]^T.
// CTA 128x128, BK=32, 8 warps (4m x 2n), 2-stage cp.async.
// Epilogue: Cf (fp32) or Ch (single fp16, scaled).
// ---------------------------------------------------------------------------
#define TILE_B   (128 * 40 * 2)            // 10240 B per 128x32 fp16 tile
#define STAGE_B  (2 * TILE_B)              // A, B
#define NSTAGE   (DMODEL / 32)             // 32

extern __shared__ char dyn_smem[];

__global__ __launch_bounds__(256, 2) void gemm_f16(
    const __half* __restrict__ A, const __half* __restrict__ B,
    float* __restrict__ Cf, __half* __restrict__ Ch, float scale)
{
    const uint32_t sb = smem_u32(dyn_smem);
    const int tid  = threadIdx.x;
    const int lane = tid & 31;
    const int wid  = tid >> 5;
    const int m0   = (wid & 3) * 32;
    const int n0   = (wid >> 2) * 64;
    const int row0 = blockIdx.y * 128;
    const int col0 = blockIdx.x * 128;

    const __half* srcs[2] = {A, B};

    float acc[2][8][4];
#pragma unroll
    for (int a = 0; a < 2; a++)
#pragma unroll
        for (int b = 0; b < 8; b++)
#pragma unroll
            for (int d = 0; d < 4; d++) acc[a][b][d] = 0.f;

    const int a_row = lane & 15;
    const int a_col = 8 * (lane >> 4);
    const int b_row = (lane & 7) + 8 * (lane >> 4);
    const int b_col = 8 * ((lane >> 3) & 1);

    auto load_stage = [&](int s) {
        const uint32_t base = sb + (uint32_t)(s & 1) * STAGE_B;
        const int k0 = s * 32;
#pragma unroll
        for (int t = 0; t < 2; t++) {
            const uint32_t tb = base + (uint32_t)t * TILE_B;
            const int gr0 = (t < 1) ? row0 : col0;
#pragma unroll
            for (int i = 0; i < 2; i++) {
                int f  = tid + i * 256;
                int r  = f >> 2;
                int ch = f & 3;
                cp_async16(tb + (uint32_t)(r * 80 + ch * 16),
                           srcs[t] + (size_t)(gr0 + r) * DMODEL + k0 + ch * 8);
            }
        }
        CP_COMMIT();
    };

    load_stage(0);

    for (int s = 0; s < NSTAGE; s++) {
        if (s + 1 < NSTAGE) { load_stage(s + 1); CP_WAIT(1); }
        else                 { CP_WAIT(0); }
        __syncthreads();

        const uint32_t base = sb + (uint32_t)(s & 1) * STAGE_B;
        const uint32_t aB = base, bB = base + TILE_B;

#pragma unroll
        for (int kk = 0; kk < 32; kk += 16) {
            uint32_t af[2][4];
#pragma unroll
            for (int mi = 0; mi < 2; mi++) {
                uint32_t off = (uint32_t)((m0 + mi * 16 + a_row) * 80 +
                                          (kk + a_col) * 2);
                ldsm_x4(af[mi], aB + off);
            }
#pragma unroll
            for (int ng = 0; ng < 4; ng++) {
                uint32_t boff = (uint32_t)((n0 + ng * 16 + b_row) * 80 +
                                           (kk + b_col) * 2);
                uint32_t bf[4];
                ldsm_x4(bf, bB + boff);
#pragma unroll
                for (int mi = 0; mi < 2; mi++) {
                    mma_f16(acc[mi][2 * ng],     af[mi], bf[0], bf[1]);
                    mma_f16(acc[mi][2 * ng + 1], af[mi], bf[2], bf[3]);
                }
            }
        }
        __syncthreads();
    }

#pragma unroll
    for (int mi = 0; mi < 2; mi++) {
        int r = row0 + m0 + mi * 16 + (lane >> 2);
#pragma unroll
        for (int nj = 0; nj < 8; nj++) {
            int c = col0 + n0 + nj * 8 + (lane & 3) * 2;
            float v0 = acc[mi][nj][0] * scale, v1 = acc[mi][nj][1] * scale;
            float v2 = acc[mi][nj][2] * scale, v3 = acc[mi][nj][3] * scale;
            if (Cf) {
                *(float2*)&Cf[(size_t)r * DMODEL + c]       = make_float2(v0, v1);
                *(float2*)&Cf[(size_t)(r + 8) * DMODEL + c] = make_float2(v2, v3);
            } else {
                *(uint32_t*)&Ch[(size_t)r * DMODEL + c]       = pack_h2(v0, v1);
                *(uint32_t*)&Ch[(size_t)(r + 8) * DMODEL + c] = pack_h2(v2, v3);
            }
        }
    }
}

// ---------------------------------------------------------------------------
// FlashAttention-2 on fp16 mma.sync, causal. All operands single fp16:
// QK^T 1-term, P.V 1-term. 256 threads (8 warps x m16), Bc=64, double-buffered.
// SMEM: Q@0 (16K), 2 x {K 8K, V 8K} @16K -> 48KB total.
// ---------------------------------------------------------------------------
#define ATT_Q    0u
#define ATT_BUF  16384u          // + (t&1)*16384; K@+0, V@+8192
#define ATT_SMEM 49152u

__global__ __launch_bounds__(256, 2) void attn_tc()
{
    const uint32_t sb = smem_u32(dyn_smem);
    const int tid  = threadIdx.x;
    const int lane = tid & 31;
    const int wid  = tid >> 5;
    const int m0   = wid * 16;
    const int bh   = blockIdx.y;
    const int base = (bh >> 4) * T_SEQ;
    const int h64  = (bh & 15) * DH;
    const int qb   = ((int)gridDim.x - 1 - (int)blockIdx.x) * 128;  // heavy first
    const int ntiles = qb / 64 + 2;

    // ---- load Q tile: 1024 16B-chunks ----
#pragma unroll
    for (int i = 0; i < 4; i++) {
        int f = tid + 256 * i;
        int r = f >> 3, ch = f & 7;
        uint32_t off = SW128((uint32_t)(r * 128 + ch * 16));
        size_t g = (size_t)(base + qb + r) * DMODEL + h64 + ch * 8;
        cp_async16(sb + ATT_Q + off, &g_Q[g]);
    }
    CP_COMMIT();

    auto load_kv = [&](int t) {
        const uint32_t bufb = sb + ATT_BUF + (uint32_t)(t & 1) * 16384u;
        const int kt = t * 64;
#pragma unroll
        for (int i = 0; i < 2; i++) {
            int f = tid + 256 * i;
            int r = f >> 3, ch = f & 7;
            uint32_t off = SW128((uint32_t)(r * 128 + ch * 16));
            size_t g = (size_t)(base + kt + r) * DMODEL + h64 + ch * 8;
            cp_async16(bufb + off,        &g_K[g]);
            cp_async16(bufb + 8192 + off, &g_V[g]);
        }
        CP_COMMIT();
    };

    load_kv(0);

    const int a_row = lane & 15;
    const int a_col = 8 * (lane >> 4);
    const int b_row = (lane & 7) + 8 * (lane >> 4);
    const int b_col = 8 * ((lane >> 3) & 1);

    // ---- hoist Q fragments into registers ----
    CP_WAIT(1);
    __syncthreads();
    uint32_t qf[4][4];
#pragma unroll
    for (int ks = 0; ks < 4; ks++) {
        uint32_t off = SW128((uint32_t)((m0 + a_row) * 128 + (ks * 16 + a_col) * 2));
        ldsm_x4(qf[ks], sb + ATT_Q + off);
    }

    float o[8][4];
#pragma unroll
    for (int b = 0; b < 8; b++)
#pragma unroll
        for (int d = 0; d < 4; d++) o[b][d] = 0.f;
    float mrow[2] = {-1e30f, -1e30f};
    float lrow[2] = {0.f, 0.f};

    for (int t = 0; t < ntiles; t++) {
        if (t + 1 < ntiles) { load_kv(t + 1); CP_WAIT(1); }
        else                 { CP_WAIT(0); }
        __syncthreads();

        const uint32_t bufb = sb + ATT_BUF + (uint32_t)(t & 1) * 16384u;
        const uint32_t Kb = bufb, Vb = bufb + 8192;
        const int kt = t * 64;

        // ---- S = Q K^T (1-term fp16) ----
        float s[8][4];
#pragma unroll
        for (int b = 0; b < 8; b++)
#pragma unroll
            for (int d = 0; d < 4; d++) s[b][d] = 0.f;

#pragma unroll
        for (int ks = 0; ks < 4; ks++) {
#pragma unroll
            for (int jp = 0; jp < 4; jp++) {
                uint32_t boff = SW128((uint32_t)((jp * 16 + b_row) * 128 +
                                                 (ks * 16 + b_col) * 2));
                uint32_t kh[4];
                ldsm_x4(kh, Kb + boff);
                mma_f16(s[2 * jp],     qf[ks], kh[0], kh[1]);
                mma_f16(s[2 * jp + 1], qf[ks], kh[2], kh[3]);
            }
        }

        // ---- causal mask (only the two diagonal-crossing tiles) ----
        if (t >= ntiles - 2) {
            int rlo = qb + m0 + (lane >> 2);
#pragma unroll
            for (int j = 0; j < 8; j++) {
                int c0 = kt + j * 8 + (lane & 3) * 2;
                if (c0 > rlo)         s[j][0] = -1e30f;
                if (c0 + 1 > rlo)     s[j][1] = -1e30f;
                if (c0 > rlo + 8)     s[j][2] = -1e30f;
                if (c0 + 1 > rlo + 8) s[j][3] = -1e30f;
            }
        }

        // ---- online softmax (log2 domain; Q pre-scaled) ----
        {
            float mx0 = -1e30f, mx1 = -1e30f;
#pragma unroll
            for (int j = 0; j < 8; j++) {
                mx0 = fmaxf(mx0, fmaxf(s[j][0], s[j][1]));
                mx1 = fmaxf(mx1, fmaxf(s[j][2], s[j][3]));
            }
            mx0 = fmaxf(mx0, __shfl_xor_sync(0xffffffff, mx0, 1));
            mx0 = fmaxf(mx0, __shfl_xor_sync(0xffffffff, mx0, 2));
            mx1 = fmaxf(mx1, __shfl_xor_sync(0xffffffff, mx1, 1));
            mx1 = fmaxf(mx1, __shfl_xor_sync(0xffffffff, mx1, 2));
            float mn0 = fmaxf(mrow[0], mx0), mn1 = fmaxf(mrow[1], mx1);
            float c0 = ex2(mrow[0] - mn0),   c1 = ex2(mrow[1] - mn1);
            mrow[0] = mn0; mrow[1] = mn1;
            lrow[0] *= c0; lrow[1] *= c1;
#pragma unroll
            for (int j = 0; j < 8; j++) {
                o[j][0] *= c0; o[j][1] *= c0;
                o[j][2] *= c1; o[j][3] *= c1;
            }
            float sum0 = 0.f, sum1 = 0.f;
#pragma unroll
            for (int j = 0; j < 8; j++) {
                float p0 = ex2(s[j][0] - mn0);
                float p1 = ex2(s[j][1] - mn0);
                float p2 = ex2(s[j][2] - mn1);
                float p3 = ex2(s[j][3] - mn1);
                s[j][0] = p0; s[j][1] = p1;
                s[j][2] = p2; s[j][3] = p3;
                sum0 += p0 + p1; sum1 += p2 + p3;
            }
            lrow[0] += sum0; lrow[1] += sum1;
        }

        // ---- O += P V (1-term) ----
#pragma unroll
        for (int ks = 0; ks < 4; ks++) {
            uint32_t ph[4];
            ph[0] = pack_h2(s[2 * ks][0],     s[2 * ks][1]);
            ph[1] = pack_h2(s[2 * ks][2],     s[2 * ks][3]);
            ph[2] = pack_h2(s[2 * ks + 1][0], s[2 * ks + 1][1]);
            ph[3] = pack_h2(s[2 * ks + 1][2], s[2 * ks + 1][3]);
#pragma unroll
            for (int jp = 0; jp < 4; jp++) {
                uint32_t voff = SW128((uint32_t)((ks * 16 + a_row) * 128 +
                                                 (jp * 16 + a_col) * 2));
                uint32_t vh[4];
                ldsm_x4_t(vh, Vb + voff);
                mma_f16(o[2 * jp],     ph, vh[0], vh[1]);
                mma_f16(o[2 * jp + 1], ph, vh[2], vh[3]);
            }
        }
        __syncthreads();
    }

    // ---- finalize: z = O/l, write single fp16 Z ----
    {
        float l0 = lrow[0], l1 = lrow[1];
        l0 += __shfl_xor_sync(0xffffffff, l0, 1);
        l0 += __shfl_xor_sync(0xffffffff, l0, 2);
        l1 += __shfl_xor_sync(0xffffffff, l1, 1);
        l1 += __shfl_xor_sync(0xffffffff, l1, 2);
        float inv0 = 1.f / l0, inv1 = 1.f / l1;
        size_t rlo = (size_t)(base + qb + m0 + (lane >> 2)) * DMODEL;
        size_t rhi = rlo + 8 * DMODEL;
#pragma unroll
        for (int j = 0; j < 8; j++) {
            int c = h64 + j * 8 + (lane & 3) * 2;
            *(uint32_t*)&g_Z[rlo + c] = pack_h2(o[j][0] * inv0, o[j][1] * inv0);
            *(uint32_t*)&g_Z[rhi + c] = pack_h2(o[j][2] * inv1, o[j][3] * inv1);
        }
    }
}

// ---------------------------------------------------------------------------
extern "C" void kernel_launch(void* const* d_in, const int* in_sizes, int n_in,
                              void* d_out, int out_size)
{
    const float* x  = (const float*)d_in[0];
    const float* Wq = (const float*)d_in[1];
    const float* Wk = (const float*)d_in[2];
    const float* Wv = (const float*)d_in[3];
    const float* Wo = (const float*)d_in[4];
    float* out = (float*)d_out;

    __half *Qs, *Ks, *Vs, *xq, *Zq, *Wt;
    cudaGetSymbolAddress((void**)&Qs, g_Q);  cudaGetSymbolAddress((void**)&Ks, g_K);
    cudaGetSymbolAddress((void**)&Vs, g_V);  cudaGetSymbolAddress((void**)&xq, g_x);
    cudaGetSymbolAddress((void**)&Zq, g_Z);  cudaGetSymbolAddress((void**)&Wt, g_W);

    cudaFuncSetAttribute(gemm_f16, cudaFuncAttributeMaxDynamicSharedMemorySize,
                         2 * STAGE_B);
    cudaFuncSetAttribute(attn_tc, cudaFuncAttributeMaxDynamicSharedMemorySize,
                         ATT_SMEM);

    const size_t WSZ = (size_t)DMODEL * DMODEL;
    const int nx4 = MROWS * DMODEL / 4;

    cvt_x<<<(nx4 + 255) / 256, 256>>>(x, xq, nx4);
    split_wt_h4<<<dim3(DMODEL / 32, DMODEL / 32, 4), dim3(32, 8)>>>(Wq, Wk, Wv, Wo, Wt);

    dim3 ggrid(DMODEL / 128, MROWS / 128);   // (8, 32)
    gemm_f16<<<ggrid, 256, 2 * STAGE_B>>>(xq, Wt + 0 * WSZ, nullptr, Qs, QSCALE);
    gemm_f16<<<ggrid, 256, 2 * STAGE_B>>>(xq, Wt + 1 * WSZ, nullptr, Ks, 1.0f);
    gemm_f16<<<ggrid, 256, 2 * STAGE_B>>>(xq, Wt + 2 * WSZ, nullptr, Vs, 1.0f);

    attn_tc<<<dim3(T_SEQ / 128, NB * NH), 256, ATT_SMEM>>>();

    gemm_f16<<<ggrid, 256, 2 * STAGE_B>>>(Zq, Wt + 3 * WSZ, out, nullptr, 1.0f);
}

// round 16
// speedup vs baseline: 4.9251x; 1.1412x over previous
#include <cuda_runtime.h>
#include <cuda_fp16.h>
#include <cstdint>

#define MROWS  4096   // B*T
#define DMODEL 1024
#define T_SEQ  2048
#define NB     2
#define NH     16
#define DH     64
#define QSCALE 0.1803368801111244f   // 0.125 * log2(e)

// ---------------- scratch (__device__ globals: allocation-free rule) --------
__device__ __half g_Q [MROWS * DMODEL];                          // Q single (pre-scaled)
__device__ __half g_K [MROWS * DMODEL];                          // K single fp16
__device__ __half g_V [MROWS * DMODEL];                          // V single fp16
__device__ __half g_x [MROWS * DMODEL];                          // x single fp16
__device__ __half g_Z [MROWS * DMODEL];                          // Z single fp16
__device__ __half g_W[4][DMODEL * DMODEL];                       // transposed [N,K]

// ---------------------------------------------------------------------------
// PTX helpers (plain sm_103: cp.async, ldmatrix, mma.sync, ex2.approx)
// ---------------------------------------------------------------------------
__device__ __forceinline__ uint32_t smem_u32(const void* p) {
    uint32_t a;
    asm("{ .reg .u64 t; cvta.to.shared.u64 t, %1; cvt.u32.u64 %0, t; }"
        : "=r"(a) : "l"(p));
    return a;
}
__device__ __forceinline__ void cp_async16(uint32_t dst, const void* src) {
    asm volatile("cp.async.cg.shared.global [%0], [%1], 16;" :: "r"(dst), "l"(src));
}
#define CP_COMMIT() asm volatile("cp.async.commit_group;" ::: "memory")
#define CP_WAIT(n)  asm volatile("cp.async.wait_group %0;" :: "n"(n) : "memory")
#define SW128(off)  ((off) ^ (((off) >> 3) & 0x70))

__device__ __forceinline__ void ldsm_x4(uint32_t* r, uint32_t addr) {
    asm volatile("ldmatrix.sync.aligned.m8n8.x4.shared.b16 {%0,%1,%2,%3}, [%4];"
                 : "=r"(r[0]), "=r"(r[1]), "=r"(r[2]), "=r"(r[3]) : "r"(addr));
}
__device__ __forceinline__ void ldsm_x4_t(uint32_t* r, uint32_t addr) {
    asm volatile("ldmatrix.sync.aligned.m8n8.x4.trans.shared.b16 {%0,%1,%2,%3}, [%4];"
                 : "=r"(r[0]), "=r"(r[1]), "=r"(r[2]), "=r"(r[3]) : "r"(addr));
}
__device__ __forceinline__ void mma_f16(float* c, const uint32_t* a,
                                        uint32_t b0, uint32_t b1) {
    asm volatile(
        "mma.sync.aligned.m16n8k16.row.col.f32.f16.f16.f32 "
        "{%0,%1,%2,%3}, {%4,%5,%6,%7}, {%8,%9}, {%0,%1,%2,%3};"
        : "+f"(c[0]), "+f"(c[1]), "+f"(c[2]), "+f"(c[3])
        : "r"(a[0]), "r"(a[1]), "r"(a[2]), "r"(a[3]), "r"(b0), "r"(b1));
}
__device__ __forceinline__ float ex2(float x) {
    float r; asm("ex2.approx.f32 %0, %1;" : "=f"(r) : "f"(x)); return r;
}
__device__ __forceinline__ uint32_t pack_h2(float v0, float v1) {
    __half2 h = __floats2half2_rn(v0, v1);
    return *(uint32_t*)&h;
}

// ---------------------------------------------------------------------------
// Conversion kernels
// ---------------------------------------------------------------------------
__global__ __launch_bounds__(256) void cvt_x(const float* __restrict__ src,
                                             __half* __restrict__ dst, int n4)
{
    int i = blockIdx.x * 256 + threadIdx.x;
    if (i >= n4) return;
    float4 v = ((const float4*)src)[i];
    ((uint2*)dst)[i] = make_uint2(pack_h2(v.x, v.y), pack_h2(v.z, v.w));
}

// All 4 weights in one launch: W[K,N] fp32 -> transposed fp16 [N,K]
__global__ __launch_bounds__(256) void split_wt_h4(
    const float* __restrict__ W0, const float* __restrict__ W1,
    const float* __restrict__ W2, const float* __restrict__ W3,
    __half* __restrict__ T)
{
    __shared__ float tile[32][33];
    const float* Ws[4] = {W0, W1, W2, W3};
    const float* W = Ws[blockIdx.z];
    __half* Tz = T + (size_t)blockIdx.z * DMODEL * DMODEL;
    const int tx = threadIdx.x, ty = threadIdx.y;        // (32, 8)
    const int bn = blockIdx.x * 32, bk = blockIdx.y * 32;
#pragma unroll
    for (int j = 0; j < 32; j += 8)
        tile[ty + j][tx] = W[(size_t)(bk + ty + j) * DMODEL + bn + tx];
    __syncthreads();
#pragma unroll
    for (int j = 0; j < 32; j += 8)
        Tz[(size_t)(bn + ty + j) * DMODEL + bk + tx] = __float2half_rn(tile[tx][ty + j]);
}

// ---------------------------------------------------------------------------
// fp16 mma.sync GEMM: C = A[M,K] * B[N,K]^T.
// CTA 128x128, BK=64, 8 warps (4m x 2n -> warp 32x64), 3-stage cp.async ring.
// Rows exact 128B with SW128 swizzle. 16 barriers total (vs 32 at BK=32).
// ---------------------------------------------------------------------------
#define G_TILE   16384u                    // 128 rows x 128B
#define G_STAGE  (2 * G_TILE)              // A, B
#define G_NST    (DMODEL / 64)             // 16

extern __shared__ char dyn_smem[];

__global__ __launch_bounds__(256, 2) void gemm_f16(
    const __half* __restrict__ A, const __half* __restrict__ B,
    float* __restrict__ Cf, __half* __restrict__ Ch, float scale)
{
    const uint32_t sb = smem_u32(dyn_smem);
    const int tid  = threadIdx.x;
    const int lane = tid & 31;
    const int wid  = tid >> 5;
    const int m0   = (wid & 3) * 32;
    const int n0   = (wid >> 2) * 64;
    const int row0 = blockIdx.y * 128;
    const int col0 = blockIdx.x * 128;

    const __half* srcs[2] = {A, B};

    float acc[2][8][4];
#pragma unroll
    for (int a = 0; a < 2; a++)
#pragma unroll
        for (int b = 0; b < 8; b++)
#pragma unroll
            for (int d = 0; d < 4; d++) acc[a][b][d] = 0.f;

    const int a_row = lane & 15;
    const int a_col = 8 * (lane >> 4);
    const int b_row = (lane & 7) + 8 * (lane >> 4);
    const int b_col = 8 * ((lane >> 3) & 1);

    auto load_stage = [&](int s) {
        const uint32_t base = sb + (uint32_t)(s % 3) * G_STAGE;
        const int k0 = s * 64;
#pragma unroll
        for (int t = 0; t < 2; t++) {
            const uint32_t tb = base + (uint32_t)t * G_TILE;
            const int gr0 = (t < 1) ? row0 : col0;
            const __half* src = srcs[t];
#pragma unroll
            for (int i = 0; i < 4; i++) {
                int f  = tid + i * 256;        // 0..1023
                int r  = f >> 3;
                int ch = f & 7;
                cp_async16(tb + SW128((uint32_t)(r * 128 + ch * 16)),
                           src + (size_t)(gr0 + r) * DMODEL + k0 + ch * 8);
            }
        }
        CP_COMMIT();
    };

    load_stage(0);
    load_stage(1);

    for (int s = 0; s < G_NST; s++) {
        CP_WAIT(1);                       // stage s resident
        __syncthreads();                  // all warps done with stage s-1
        if (s + 2 < G_NST) load_stage(s + 2);   // overwrites slot of s-1: safe

        const uint32_t base = sb + (uint32_t)(s % 3) * G_STAGE;
        const uint32_t aB = base, bB = base + G_TILE;

#pragma unroll
        for (int kk = 0; kk < 64; kk += 16) {
            uint32_t af[2][4], bf[4][4];
#pragma unroll
            for (int mi = 0; mi < 2; mi++) {
                uint32_t off = SW128((uint32_t)((m0 + mi * 16 + a_row) * 128 +
                                                (kk + a_col) * 2));
                ldsm_x4(af[mi], aB + off);
            }
#pragma unroll
            for (int ng = 0; ng < 4; ng++) {
                uint32_t boff = SW128((uint32_t)((n0 + ng * 16 + b_row) * 128 +
                                                 (kk + b_col) * 2));
                ldsm_x4(bf[ng], bB + boff);
            }
#pragma unroll
            for (int ng = 0; ng < 4; ng++)
#pragma unroll
                for (int mi = 0; mi < 2; mi++) {
                    mma_f16(acc[mi][2 * ng],     af[mi], bf[ng][0], bf[ng][1]);
                    mma_f16(acc[mi][2 * ng + 1], af[mi], bf[ng][2], bf[ng][3]);
                }
        }
    }

#pragma unroll
    for (int mi = 0; mi < 2; mi++) {
        int r = row0 + m0 + mi * 16 + (lane >> 2);
#pragma unroll
        for (int nj = 0; nj < 8; nj++) {
            int c = col0 + n0 + nj * 8 + (lane & 3) * 2;
            float v0 = acc[mi][nj][0] * scale, v1 = acc[mi][nj][1] * scale;
            float v2 = acc[mi][nj][2] * scale, v3 = acc[mi][nj][3] * scale;
            if (Cf) {
                *(float2*)&Cf[(size_t)r * DMODEL + c]       = make_float2(v0, v1);
                *(float2*)&Cf[(size_t)(r + 8) * DMODEL + c] = make_float2(v2, v3);
            } else {
                *(uint32_t*)&Ch[(size_t)r * DMODEL + c]       = pack_h2(v0, v1);
                *(uint32_t*)&Ch[(size_t)(r + 8) * DMODEL + c] = pack_h2(v2, v3);
            }
        }
    }
}

// ---------------------------------------------------------------------------
// FlashAttention-2 on fp16 mma.sync, causal (unchanged from R14 WIN).
// QK^T 1-term, P.V 1-term. 256 threads (8 warps x m16), Bc=64, double-buffered.
// ---------------------------------------------------------------------------
#define ATT_Q    0u
#define ATT_BUF  16384u          // + (t&1)*16384; K@+0, V@+8192
#define ATT_SMEM 49152u

__global__ __launch_bounds__(256, 2) void attn_tc()
{
    const uint32_t sb = smem_u32(dyn_smem);
    const int tid  = threadIdx.x;
    const int lane = tid & 31;
    const int wid  = tid >> 5;
    const int m0   = wid * 16;
    const int bh   = blockIdx.y;
    const int base = (bh >> 4) * T_SEQ;
    const int h64  = (bh & 15) * DH;
    const int qb   = ((int)gridDim.x - 1 - (int)blockIdx.x) * 128;  // heavy first
    const int ntiles = qb / 64 + 2;

    // ---- load Q tile ----
#pragma unroll
    for (int i = 0; i < 4; i++) {
        int f = tid + 256 * i;
        int r = f >> 3, ch = f & 7;
        uint32_t off = SW128((uint32_t)(r * 128 + ch * 16));
        size_t g = (size_t)(base + qb + r) * DMODEL + h64 + ch * 8;
        cp_async16(sb + ATT_Q + off, &g_Q[g]);
    }
    CP_COMMIT();

    auto load_kv = [&](int t) {
        const uint32_t bufb = sb + ATT_BUF + (uint32_t)(t & 1) * 16384u;
        const int kt = t * 64;
#pragma unroll
        for (int i = 0; i < 2; i++) {
            int f = tid + 256 * i;
            int r = f >> 3, ch = f & 7;
            uint32_t off = SW128((uint32_t)(r * 128 + ch * 16));
            size_t g = (size_t)(base + kt + r) * DMODEL + h64 + ch * 8;
            cp_async16(bufb + off,        &g_K[g]);
            cp_async16(bufb + 8192 + off, &g_V[g]);
        }
        CP_COMMIT();
    };

    load_kv(0);

    const int a_row = lane & 15;
    const int a_col = 8 * (lane >> 4);
    const int b_row = (lane & 7) + 8 * (lane >> 4);
    const int b_col = 8 * ((lane >> 3) & 1);

    // ---- hoist Q fragments into registers ----
    CP_WAIT(1);
    __syncthreads();
    uint32_t qf[4][4];
#pragma unroll
    for (int ks = 0; ks < 4; ks++) {
        uint32_t off = SW128((uint32_t)((m0 + a_row) * 128 + (ks * 16 + a_col) * 2));
        ldsm_x4(qf[ks], sb + ATT_Q + off);
    }

    float o[8][4];
#pragma unroll
    for (int b = 0; b < 8; b++)
#pragma unroll
        for (int d = 0; d < 4; d++) o[b][d] = 0.f;
    float mrow[2] = {-1e30f, -1e30f};
    float lrow[2] = {0.f, 0.f};

    for (int t = 0; t < ntiles; t++) {
        if (t + 1 < ntiles) { load_kv(t + 1); CP_WAIT(1); }
        else                 { CP_WAIT(0); }
        __syncthreads();

        const uint32_t bufb = sb + ATT_BUF + (uint32_t)(t & 1) * 16384u;
        const uint32_t Kb = bufb, Vb = bufb + 8192;
        const int kt = t * 64;

        // ---- S = Q K^T (1-term fp16) ----
        float s[8][4];
#pragma unroll
        for (int b = 0; b < 8; b++)
#pragma unroll
            for (int d = 0; d < 4; d++) s[b][d] = 0.f;

#pragma unroll
        for (int ks = 0; ks < 4; ks++) {
#pragma unroll
            for (int jp = 0; jp < 4; jp++) {
                uint32_t boff = SW128((uint32_t)((jp * 16 + b_row) * 128 +
                                                 (ks * 16 + b_col) * 2));
                uint32_t kh[4];
                ldsm_x4(kh, Kb + boff);
                mma_f16(s[2 * jp],     qf[ks], kh[0], kh[1]);
                mma_f16(s[2 * jp + 1], qf[ks], kh[2], kh[3]);
            }
        }

        // ---- causal mask (only the two diagonal-crossing tiles) ----
        if (t >= ntiles - 2) {
            int rlo = qb + m0 + (lane >> 2);
#pragma unroll
            for (int j = 0; j < 8; j++) {
                int c0 = kt + j * 8 + (lane & 3) * 2;
                if (c0 > rlo)         s[j][0] = -1e30f;
                if (c0 + 1 > rlo)     s[j][1] = -1e30f;
                if (c0 > rlo + 8)     s[j][2] = -1e30f;
                if (c0 + 1 > rlo + 8) s[j][3] = -1e30f;
            }
        }

        // ---- online softmax (log2 domain; Q pre-scaled) ----
        {
            float mx0 = -1e30f, mx1 = -1e30f;
#pragma unroll
            for (int j = 0; j < 8; j++) {
                mx0 = fmaxf(mx0, fmaxf(s[j][0], s[j][1]));
                mx1 = fmaxf(mx1, fmaxf(s[j][2], s[j][3]));
            }
            mx0 = fmaxf(mx0, __shfl_xor_sync(0xffffffff, mx0, 1));
            mx0 = fmaxf(mx0, __shfl_xor_sync(0xffffffff, mx0, 2));
            mx1 = fmaxf(mx1, __shfl_xor_sync(0xffffffff, mx1, 1));
            mx1 = fmaxf(mx1, __shfl_xor_sync(0xffffffff, mx1, 2));
            float mn0 = fmaxf(mrow[0], mx0), mn1 = fmaxf(mrow[1], mx1);
            float c0 = ex2(mrow[0] - mn0),   c1 = ex2(mrow[1] - mn1);
            mrow[0] = mn0; mrow[1] = mn1;
            lrow[0] *= c0; lrow[1] *= c1;
#pragma unroll
            for (int j = 0; j < 8; j++) {
                o[j][0] *= c0; o[j][1] *= c0;
                o[j][2] *= c1; o[j][3] *= c1;
            }
            float sum0 = 0.f, sum1 = 0.f;
#pragma unroll
            for (int j = 0; j < 8; j++) {
                float p0 = ex2(s[j][0] - mn0);
                float p1 = ex2(s[j][1] - mn0);
                float p2 = ex2(s[j][2] - mn1);
                float p3 = ex2(s[j][3] - mn1);
                s[j][0] = p0; s[j][1] = p1;
                s[j][2] = p2; s[j][3] = p3;
                sum0 += p0 + p1; sum1 += p2 + p3;
            }
            lrow[0] += sum0; lrow[1] += sum1;
        }

        // ---- O += P V (1-term) ----
#pragma unroll
        for (int ks = 0; ks < 4; ks++) {
            uint32_t ph[4];
            ph[0] = pack_h2(s[2 * ks][0],     s[2 * ks][1]);
            ph[1] = pack_h2(s[2 * ks][2],     s[2 * ks][3]);
            ph[2] = pack_h2(s[2 * ks + 1][0], s[2 * ks + 1][1]);
            ph[3] = pack_h2(s[2 * ks + 1][2], s[2 * ks + 1][3]);
#pragma unroll
            for (int jp = 0; jp < 4; jp++) {
                uint32_t voff = SW128((uint32_t)((ks * 16 + a_row) * 128 +
                                                 (jp * 16 + a_col) * 2));
                uint32_t vh[4];
                ldsm_x4_t(vh, Vb + voff);
                mma_f16(o[2 * jp],     ph, vh[0], vh[1]);
                mma_f16(o[2 * jp + 1], ph, vh[2], vh[3]);
            }
        }
        __syncthreads();
    }

    // ---- finalize: z = O/l, write single fp16 Z ----
    {
        float l0 = lrow[0], l1 = lrow[1];
        l0 += __shfl_xor_sync(0xffffffff, l0, 1);
        l0 += __shfl_xor_sync(0xffffffff, l0, 2);
        l1 += __shfl_xor_sync(0xffffffff, l1, 1);
        l1 += __shfl_xor_sync(0xffffffff, l1, 2);
        float inv0 = 1.f / l0, inv1 = 1.f / l1;
        size_t rlo = (size_t)(base + qb + m0 + (lane >> 2)) * DMODEL;
        size_t rhi = rlo + 8 * DMODEL;
#pragma unroll
        for (int j = 0; j < 8; j++) {
            int c = h64 + j * 8 + (lane & 3) * 2;
            *(uint32_t*)&g_Z[rlo + c] = pack_h2(o[j][0] * inv0, o[j][1] * inv0);
            *(uint32_t*)&g_Z[rhi + c] = pack_h2(o[j][2] * inv1, o[j][3] * inv1);
        }
    }
}

// ---------------------------------------------------------------------------
extern "C" void kernel_launch(void* const* d_in, const int* in_sizes, int n_in,
                              void* d_out, int out_size)
{
    const float* x  = (const float*)d_in[0];
    const float* Wq = (const float*)d_in[1];
    const float* Wk = (const float*)d_in[2];
    const float* Wv = (const float*)d_in[3];
    const float* Wo = (const float*)d_in[4];
    float* out = (float*)d_out;

    __half *Qs, *Ks, *Vs, *xq, *Zq, *Wt;
    cudaGetSymbolAddress((void**)&Qs, g_Q);  cudaGetSymbolAddress((void**)&Ks, g_K);
    cudaGetSymbolAddress((void**)&Vs, g_V);  cudaGetSymbolAddress((void**)&xq, g_x);
    cudaGetSymbolAddress((void**)&Zq, g_Z);  cudaGetSymbolAddress((void**)&Wt, g_W);

    cudaFuncSetAttribute(gemm_f16, cudaFuncAttributeMaxDynamicSharedMemorySize,
                         3 * G_STAGE);
    cudaFuncSetAttribute(attn_tc, cudaFuncAttributeMaxDynamicSharedMemorySize,
                         ATT_SMEM);

    const size_t WSZ = (size_t)DMODEL * DMODEL;
    const int nx4 = MROWS * DMODEL / 4;

    cvt_x<<<(nx4 + 255) / 256, 256>>>(x, xq, nx4);
    split_wt_h4<<<dim3(DMODEL / 32, DMODEL / 32, 4), dim3(32, 8)>>>(Wq, Wk, Wv, Wo, Wt);

    dim3 ggrid(DMODEL / 128, MROWS / 128);   // (8, 32)
    gemm_f16<<<ggrid, 256, 3 * G_STAGE>>>(xq, Wt + 0 * WSZ, nullptr, Qs, QSCALE);
    gemm_f16<<<ggrid, 256, 3 * G_STAGE>>>(xq, Wt + 1 * WSZ, nullptr, Ks, 1.0f);
    gemm_f16<<<ggrid, 256, 3 * G_STAGE>>>(xq, Wt + 2 * WSZ, nullptr, Vs, 1.0f);

    attn_tc<<<dim3(T_SEQ / 128, NB * NH), 256, ATT_SMEM>>>();

    gemm_f16<<<ggrid, 256, 3 * G_STAGE>>>(Zq, Wt + 3 * WSZ, out, nullptr, 1.0f);
}